// round 1
// baseline (speedup 1.0000x reference)
#include <cuda_runtime.h>

#define LRELU_SLOPE 0.2f

// Scratch: [dir][graph(256)][node(64)][ch(64)]
__device__ float g_feat[2][256 * 64 * 64];
__device__ float g_gout[2][256 * 64 * 64];

__device__ __forceinline__ float leaky(float v) { return v >= 0.f ? v : LRELU_SLOPE * v; }

__device__ __forceinline__ void f4fma(float a, const float4& b, float4& c) {
    c.x = fmaf(a, b.x, c.x);
    c.y = fmaf(a, b.y, c.y);
    c.z = fmaf(a, b.z, c.z);
    c.w = fmaf(a, b.w, c.w);
}

__device__ __forceinline__ float gc(const float4& v, int j) {
    switch (j) { case 0: return v.x; case 1: return v.y; case 2: return v.z; default: return v.w; }
}

// ============================================================================
// Kernel 1: LayerNorm (over C) + 1x1 conv + leaky + split into strip layouts
// One block per (b, h) row: tile [128 ch][64 w]
// ============================================================================
__global__ __launch_bounds__(256) void k_pre(
    const float* __restrict__ x, const float* __restrict__ norm_w,
    const float* __restrict__ norm_b, const float* __restrict__ conv_w,
    const float* __restrict__ conv_b)
{
    extern __shared__ float sm[];
    float* xs = sm;                  // [128][64]
    float* ws = sm + 128 * 64;       // [128 c][132 pad] transposed conv_w
    float* mu = ws + 128 * 132;      // [64]
    float* rs = mu + 64;             // [64]
    const int tid = threadIdx.x;
    const int b = blockIdx.x >> 6, h = blockIdx.x & 63;
    const float* xblk = x + (size_t)b * 128 * 4096 + h * 64;

    for (int i = tid; i < 128 * 64; i += 256) {
        int c = i >> 6, w = i & 63;
        xs[i] = xblk[c * 4096 + w];
    }
    for (int i = tid; i < 128 * 128; i += 256) {
        int oc = i >> 7, c = i & 127;
        ws[c * 132 + oc] = conv_w[i];
    }
    __syncthreads();

    if (tid < 64) {
        float s = 0.f, s2 = 0.f;
#pragma unroll 8
        for (int c = 0; c < 128; c++) { float v = xs[c * 64 + tid]; s += v; s2 += v * v; }
        float m = s * 0.0078125f;
        float var = s2 * 0.0078125f - m * m;
        mu[tid] = m;
        rs[tid] = rsqrtf(var + 1e-5f);
    }
    __syncthreads();
    for (int i = tid; i < 128 * 64; i += 256) {
        int c = i >> 6, w = i & 63;
        xs[i] = (xs[i] - mu[w]) * rs[w] * norm_w[c] + norm_b[c];
    }
    __syncthreads();

    // GEMM: y[oc][w] = conv_w[oc][:] . xn[:][w]; thread tile 8 oc x 4 w
    const int oc0 = (tid >> 4) * 8;
    const int w0 = (tid & 15) * 4;
    float4 acc[8];
#pragma unroll
    for (int i = 0; i < 8; i++) acc[i] = make_float4(0.f, 0.f, 0.f, 0.f);
#pragma unroll 4
    for (int c = 0; c < 128; c++) {
        float4 a0 = *(const float4*)(ws + c * 132 + oc0);
        float4 a1 = *(const float4*)(ws + c * 132 + oc0 + 4);
        float4 bv = *(const float4*)(xs + c * 64 + w0);
        f4fma(a0.x, bv, acc[0]); f4fma(a0.y, bv, acc[1]);
        f4fma(a0.z, bv, acc[2]); f4fma(a0.w, bv, acc[3]);
        f4fma(a1.x, bv, acc[4]); f4fma(a1.y, bv, acc[5]);
        f4fma(a1.z, bv, acc[6]); f4fma(a1.w, bv, acc[7]);
    }
#pragma unroll
    for (int i = 0; i < 8; i++) {
        float bia = conv_b[oc0 + i];
        acc[i].x = leaky(acc[i].x + bia);
        acc[i].y = leaky(acc[i].y + bia);
        acc[i].z = leaky(acc[i].z + bia);
        acc[i].w = leaky(acc[i].w + bia);
    }
    if (oc0 < 64) {
        // f_h: graph = b*64+h = blockIdx.x, node = w, ch = oc
#pragma unroll
        for (int j = 0; j < 4; j++) {
            int w = w0 + j;
            float* dst = g_feat[0] + ((size_t)blockIdx.x * 64 + w) * 64 + oc0;
            float4 v0 = make_float4(gc(acc[0], j), gc(acc[1], j), gc(acc[2], j), gc(acc[3], j));
            float4 v1 = make_float4(gc(acc[4], j), gc(acc[5], j), gc(acc[6], j), gc(acc[7], j));
            *(float4*)dst = v0;
            *(float4*)(dst + 4) = v1;
        }
    } else {
        // f_v: graph = b*64+w, node = h, ch = oc-64
#pragma unroll
        for (int j = 0; j < 4; j++) {
            int w = w0 + j;
            float* dst = g_feat[1] + ((size_t)(b * 64 + w) * 64 + h) * 64 + (oc0 - 64);
            float4 v0 = make_float4(gc(acc[0], j), gc(acc[1], j), gc(acc[2], j), gc(acc[3], j));
            float4 v1 = make_float4(gc(acc[4], j), gc(acc[5], j), gc(acc[6], j), gc(acc[7], j));
            *(float4*)dst = v0;
            *(float4*)(dst + 4) = v1;
        }
    }
}

// ============================================================================
// GCM kernel: one block per (graph, ch-tile of 32, direction)
// State X[64 nodes][256 cols=32ch*8F] in smem; temp U same shape.
// ============================================================================

// dst[l][col] (+)= sum_m adj[l][m] * src[m][col]
// thread tile: rows l0..l0+7 (warp-uniform), cols {c0..c0+3} U {128+c0..128+c0+3}
template <bool ACC>
__device__ __forceinline__ void adj_gemm(const float* __restrict__ adjT,
                                         const float* __restrict__ src,
                                         float* __restrict__ dst, int l0, int c0)
{
    float4 acc0[8], acc1[8];
#pragma unroll
    for (int i = 0; i < 8; i++) {
        acc0[i] = make_float4(0.f, 0.f, 0.f, 0.f);
        acc1[i] = make_float4(0.f, 0.f, 0.f, 0.f);
    }
#pragma unroll 8
    for (int m = 0; m < 64; m++) {
        float4 b0 = *(const float4*)(src + m * 256 + c0);
        float4 b1 = *(const float4*)(src + m * 256 + c0 + 128);
        float4 a0 = *(const float4*)(adjT + m * 68 + l0);
        float4 a1 = *(const float4*)(adjT + m * 68 + l0 + 4);
        f4fma(a0.x, b0, acc0[0]); f4fma(a0.x, b1, acc1[0]);
        f4fma(a0.y, b0, acc0[1]); f4fma(a0.y, b1, acc1[1]);
        f4fma(a0.z, b0, acc0[2]); f4fma(a0.z, b1, acc1[2]);
        f4fma(a0.w, b0, acc0[3]); f4fma(a0.w, b1, acc1[3]);
        f4fma(a1.x, b0, acc0[4]); f4fma(a1.x, b1, acc1[4]);
        f4fma(a1.y, b0, acc0[5]); f4fma(a1.y, b1, acc1[5]);
        f4fma(a1.z, b0, acc0[6]); f4fma(a1.z, b1, acc1[6]);
        f4fma(a1.w, b0, acc0[7]); f4fma(a1.w, b1, acc1[7]);
    }
#pragma unroll
    for (int i = 0; i < 8; i++) {
        float* d0 = dst + (l0 + i) * 256 + c0;
        float* d1 = d0 + 128;
        if (ACC) {
            float4 o0 = *(float4*)d0, o1 = *(float4*)d1;
            acc0[i].x += o0.x; acc0[i].y += o0.y; acc0[i].z += o0.z; acc0[i].w += o0.w;
            acc1[i].x += o1.x; acc1[i].y += o1.y; acc1[i].z += o1.z; acc1[i].w += o1.w;
        }
        *(float4*)d0 = acc0[i];
        *(float4*)d1 = acc1[i];
    }
}

// In-place feature mix: B[l][c*8+fo] = (leaky?)( sum_fi B[l][c*8+fi] * W[fi][fo] )
// Thread owns 8 (l,c) pairs exclusively -> in-place safe.
template <bool LRELU>
__device__ __forceinline__ void fmix(float* __restrict__ B, const float* __restrict__ W, int tid)
{
    float4 w0r[8], w1r[8];
#pragma unroll
    for (int fi = 0; fi < 8; fi++) {
        w0r[fi] = *(const float4*)(W + fi * 8);
        w1r[fi] = *(const float4*)(W + fi * 8 + 4);
    }
#pragma unroll
    for (int p = 0; p < 8; p++) {
        int id = tid + p * 256;
        int l = id >> 5, c = id & 31;
        float* ptr = B + l * 256 + c * 8;
        float4 v0 = *(float4*)ptr, v1 = *(float4*)(ptr + 4);
        float vi[8] = {v0.x, v0.y, v0.z, v0.w, v1.x, v1.y, v1.z, v1.w};
        float4 o0 = make_float4(0.f, 0.f, 0.f, 0.f), o1 = o0;
#pragma unroll
        for (int fi = 0; fi < 8; fi++) { f4fma(vi[fi], w0r[fi], o0); f4fma(vi[fi], w1r[fi], o1); }
        if (LRELU) {
            o0.x = leaky(o0.x); o0.y = leaky(o0.y); o0.z = leaky(o0.z); o0.w = leaky(o0.w);
            o1.x = leaky(o1.x); o1.y = leaky(o1.y); o1.z = leaky(o1.z); o1.w = leaky(o1.w);
        }
        *(float4*)ptr = o0;
        *(float4*)(ptr + 4) = o1;
    }
}

// g[i] = sum_m adj[l0+i][m] * P[m][c]   (P compact [64][32])
__device__ __forceinline__ void small_adj(const float* __restrict__ adjT,
                                          const float* __restrict__ P,
                                          float g[8], int l0, int c)
{
#pragma unroll
    for (int i = 0; i < 8; i++) g[i] = 0.f;
#pragma unroll 8
    for (int m = 0; m < 64; m++) {
        float fv = P[m * 32 + c];
        float4 a0 = *(const float4*)(adjT + m * 68 + l0);
        float4 a1 = *(const float4*)(adjT + m * 68 + l0 + 4);
        g[0] = fmaf(a0.x, fv, g[0]); g[1] = fmaf(a0.y, fv, g[1]);
        g[2] = fmaf(a0.z, fv, g[2]); g[3] = fmaf(a0.w, fv, g[3]);
        g[4] = fmaf(a1.x, fv, g[4]); g[5] = fmaf(a1.y, fv, g[5]);
        g[6] = fmaf(a1.z, fv, g[6]); g[7] = fmaf(a1.w, fv, g[7]);
    }
}

__global__ __launch_bounds__(256) void k_gcm(
    const float* __restrict__ adj_h, const float* __restrict__ adj_v,
    const float* __restrict__ head_h, const float* __restrict__ tail_h,
    const float* __restrict__ w1_h, const float* __restrict__ w2_h,
    const float* __restrict__ head_v, const float* __restrict__ tail_v,
    const float* __restrict__ w1_v, const float* __restrict__ w2_v)
{
    extern __shared__ float sm[];
    float* adjT = sm;                // [64 m][68 pad]  adjT[m][l] = adj[l][m]
    float* X = adjT + 64 * 68;       // [64][256]
    float* U = X + 64 * 256;         // [64][256] (also holds compact [64][32] feat / tail)
    float* WB = U + 64 * 256;        // 8 head + 8 tail + 256 w1 + 256 w2 = 528
    const int tid = threadIdx.x;
    const int graph = blockIdx.x, ct = blockIdx.y, dir = blockIdx.z;
    const float* adj = dir ? adj_v : adj_h;
    const float* hw = dir ? head_v : head_h;
    const float* tw = dir ? tail_v : tail_h;
    const float* w1 = dir ? w1_v : w1_h;
    const float* w2 = dir ? w2_v : w2_h;
    const float* feat = g_feat[dir] + (size_t)graph * 4096 + ct * 32;
    float* gout = g_gout[dir] + (size_t)graph * 4096 + ct * 32;

    for (int i = tid; i < 4096; i += 256) {
        int l = i >> 6, m = i & 63;
        adjT[m * 68 + l] = adj[i];
    }
    for (int i = tid; i < 528; i += 256) {
        float v;
        if (i < 8) v = hw[i];
        else if (i < 16) v = tw[i - 8];
        else if (i < 272) v = w1[i - 16];
        else v = w2[i - 272];
        WB[i] = v;
    }
    for (int i = tid; i < 2048; i += 256) {
        int m = i >> 5, c = i & 31;
        U[m * 32 + c] = feat[m * 64 + c];
    }
    __syncthreads();

    const int lane = tid & 31, wid = tid >> 5;
    const int l0 = wid * 8;
    const int c0 = lane * 4;

    // head: X[l][c*8+f] = (adj @ feat)[l][c] * head_w[f]
    {
        float g[8];
        small_adj(adjT, U, g, l0, lane);
        float hwr[8];
#pragma unroll
        for (int f = 0; f < 8; f++) hwr[f] = WB[f];
#pragma unroll
        for (int i = 0; i < 8; i++) {
            float* dst = X + (l0 + i) * 256 + lane * 8;
            *(float4*)dst = make_float4(g[i] * hwr[0], g[i] * hwr[1], g[i] * hwr[2], g[i] * hwr[3]);
            *(float4*)(dst + 4) = make_float4(g[i] * hwr[4], g[i] * hwr[5], g[i] * hwr[6], g[i] * hwr[7]);
        }
    }
    __syncthreads();

    // ResGCN body: X += adj @ ( leaky( (adj@X) W1 ) W2 )   [adj commutes with W]
    for (int it = 0; it < 4; it++) {
        adj_gemm<false>(adjT, X, U, l0, c0);
        __syncthreads();
        fmix<true>(U, WB + 16 + it * 64, tid);
        __syncthreads();
        fmix<false>(U, WB + 272 + it * 64, tid);
        __syncthreads();
        adj_gemm<true>(adjT, U, X, l0, c0);
        __syncthreads();
    }

    // tail: p[m][c] = sum_f X[m][c*8+f] * tail_w[f]  (compact into U)
    {
        float twr[8];
#pragma unroll
        for (int f = 0; f < 8; f++) twr[f] = WB[8 + f];
#pragma unroll
        for (int p = 0; p < 8; p++) {
            int id = tid + p * 256;
            int m = id >> 5, c = id & 31;
            const float* ptr = X + m * 256 + c * 8;
            float4 v0 = *(const float4*)ptr, v1 = *(const float4*)(ptr + 4);
            float s = v0.x * twr[0] + v0.y * twr[1] + v0.z * twr[2] + v0.w * twr[3]
                    + v1.x * twr[4] + v1.y * twr[5] + v1.z * twr[6] + v1.w * twr[7];
            U[m * 32 + c] = s;
        }
    }
    __syncthreads();
    // out[l][c] = leaky( (adj @ p)[l][c] )
    {
        float g[8];
        small_adj(adjT, U, g, l0, lane);
#pragma unroll
        for (int i = 0; i < 8; i++) gout[(l0 + i) * 64 + lane] = leaky(g[i]);
    }
}

// ============================================================================
// Kernel 3: gather attn + fuse 1x1 conv + bias + residual
// ============================================================================
__global__ __launch_bounds__(256) void k_fuse(
    const float* __restrict__ x, const float* __restrict__ fuse_w,
    const float* __restrict__ fuse_b, float* __restrict__ out)
{
    extern __shared__ float sm[];
    float* as = sm;                 // [128 c][68 pad] attn tile
    float* ws = sm + 128 * 68;      // [128 c][132 pad] transposed fuse_w
    const int tid = threadIdx.x;
    const int b = blockIdx.x >> 6, h = blockIdx.x & 63;

    const float* gh = g_gout[0] + (size_t)blockIdx.x * 4096;  // graph (b,h): [w][c]
    for (int i = tid; i < 4096; i += 256) {
        int w = i >> 6, c = i & 63;
        as[c * 68 + w] = gh[i];
    }
    const float* gvbase = g_gout[1] + (size_t)b * 64 * 4096 + h * 64;  // graph (b,w): [h][c]
    for (int i = tid; i < 4096; i += 256) {
        int w = i >> 6, c = i & 63;
        as[(64 + c) * 68 + w] = gvbase[(size_t)w * 4096 + c];
    }
    for (int i = tid; i < 128 * 128; i += 256) {
        int oc = i >> 7, c = i & 127;
        ws[c * 132 + oc] = fuse_w[i];
    }
    __syncthreads();

    const int oc0 = (tid >> 4) * 8;
    const int w0 = (tid & 15) * 4;
    float4 acc[8];
#pragma unroll
    for (int i = 0; i < 8; i++) acc[i] = make_float4(0.f, 0.f, 0.f, 0.f);
#pragma unroll 4
    for (int c = 0; c < 128; c++) {
        float4 a0 = *(const float4*)(ws + c * 132 + oc0);
        float4 a1 = *(const float4*)(ws + c * 132 + oc0 + 4);
        float4 bv = *(const float4*)(as + c * 68 + w0);
        f4fma(a0.x, bv, acc[0]); f4fma(a0.y, bv, acc[1]);
        f4fma(a0.z, bv, acc[2]); f4fma(a0.w, bv, acc[3]);
        f4fma(a1.x, bv, acc[4]); f4fma(a1.y, bv, acc[5]);
        f4fma(a1.z, bv, acc[6]); f4fma(a1.w, bv, acc[7]);
    }
    const float* xblk = x + (size_t)b * 128 * 4096 + h * 64;
    float* oblk = out + (size_t)b * 128 * 4096 + h * 64;
#pragma unroll
    for (int i = 0; i < 8; i++) {
        int oc = oc0 + i;
        float bia = fuse_b[oc];
        float4 xv = *(const float4*)(xblk + (size_t)oc * 4096 + w0);
        float4 o = make_float4(acc[i].x + bia + xv.x, acc[i].y + bia + xv.y,
                               acc[i].z + bia + xv.z, acc[i].w + bia + xv.w);
        *(float4*)(oblk + (size_t)oc * 4096 + w0) = o;
    }
}

extern "C" void kernel_launch(void* const* d_in, const int* in_sizes, int n_in,
                              void* d_out, int out_size)
{
    const float* x      = (const float*)d_in[0];
    const float* adj_h  = (const float*)d_in[1];
    const float* adj_v  = (const float*)d_in[2];
    const float* norm_w = (const float*)d_in[3];
    const float* norm_b = (const float*)d_in[4];
    const float* conv_w = (const float*)d_in[5];
    const float* conv_b = (const float*)d_in[6];
    const float* fuse_w = (const float*)d_in[7];
    const float* fuse_b = (const float*)d_in[8];
    const float* head_h = (const float*)d_in[9];
    const float* tail_h = (const float*)d_in[10];
    const float* w1_h   = (const float*)d_in[11];
    const float* w2_h   = (const float*)d_in[12];
    const float* head_v = (const float*)d_in[13];
    const float* tail_v = (const float*)d_in[14];
    const float* w1_v   = (const float*)d_in[15];
    const float* w2_v   = (const float*)d_in[16];
    float* out = (float*)d_out;

    const size_t s_pre  = (size_t)(128 * 64 + 128 * 132 + 128) * sizeof(float);   // ~101 KB
    const size_t s_gcm  = (size_t)(64 * 68 + 2 * 64 * 256 + 528) * sizeof(float); // ~150 KB
    const size_t s_fuse = (size_t)(128 * 68 + 128 * 132) * sizeof(float);         // ~102 KB
    cudaFuncSetAttribute(k_pre, cudaFuncAttributeMaxDynamicSharedMemorySize, (int)s_pre);
    cudaFuncSetAttribute(k_gcm, cudaFuncAttributeMaxDynamicSharedMemorySize, (int)s_gcm);
    cudaFuncSetAttribute(k_fuse, cudaFuncAttributeMaxDynamicSharedMemorySize, (int)s_fuse);

    k_pre<<<256, 256, s_pre>>>(x, norm_w, norm_b, conv_w, conv_b);
    k_gcm<<<dim3(256, 2, 2), 256, s_gcm>>>(adj_h, adj_v, head_h, tail_h, w1_h, w2_h,
                                           head_v, tail_v, w1_v, w2_v);
    k_fuse<<<256, 256, s_fuse>>>(x, fuse_w, fuse_b, out);
}

// round 5
// speedup vs baseline: 1.2826x; 1.2826x over previous
#include <cuda_runtime.h>
#include <cuda_bf16.h>
#include <cstdint>

#define LRELU_SLOPE 0.2f

// Scratch: [dir][graph(256)][node(64)][ch(64)]
__device__ float g_feat[2][256 * 64 * 64];
__device__ float g_gout[2][256 * 64 * 64];

__device__ __forceinline__ float leaky(float v) { return v >= 0.f ? v : LRELU_SLOPE * v; }

__device__ __forceinline__ void f4fma(float a, const float4& b, float4& c) {
    c.x = fmaf(a, b.x, c.x); c.y = fmaf(a, b.y, c.y);
    c.z = fmaf(a, b.z, c.z); c.w = fmaf(a, b.w, c.w);
}
__device__ __forceinline__ float gc(const float4& v, int j) {
    switch (j) { case 0: return v.x; case 1: return v.y; case 2: return v.z; default: return v.w; }
}

__device__ __forceinline__ uint32_t smem_u32(const void* p) {
    uint32_t a;
    asm("{ .reg .u64 t; cvta.to.shared.u64 t, %1; cvt.u32.u64 %0, t; }" : "=r"(a) : "l"(p));
    return a;
}
#define SW128(o) ((o) ^ (((o) >> 3) & 0x70))

__device__ __forceinline__ void ldsm4(uint32_t r[4], uint32_t addr) {
    asm volatile("ldmatrix.sync.aligned.m8n8.x4.shared.b16 {%0,%1,%2,%3}, [%4];"
                 : "=r"(r[0]), "=r"(r[1]), "=r"(r[2]), "=r"(r[3]) : "r"(addr));
}
__device__ __forceinline__ void mma16816(float c[4], const uint32_t a[4], uint32_t b0, uint32_t b1) {
    asm volatile(
        "mma.sync.aligned.m16n8k16.row.col.f32.bf16.bf16.f32 "
        "{%0,%1,%2,%3}, {%4,%5,%6,%7}, {%8,%9}, {%0,%1,%2,%3};"
        : "+f"(c[0]), "+f"(c[1]), "+f"(c[2]), "+f"(c[3])
        : "r"(a[0]), "r"(a[1]), "r"(a[2]), "r"(a[3]), "r"(b0), "r"(b1));
}

// ============================================================================
// Kernel 1: LayerNorm + 1x1 conv + leaky + strip split
// ============================================================================
__global__ __launch_bounds__(256) void k_pre(
    const float* __restrict__ x, const float* __restrict__ norm_w,
    const float* __restrict__ norm_b, const float* __restrict__ conv_w,
    const float* __restrict__ conv_b)
{
    extern __shared__ float sm_pre[];
    float* xs = sm_pre;
    float* ws = sm_pre + 128 * 64;
    float* mu = ws + 128 * 132;
    float* rs = mu + 64;
    const int tid = threadIdx.x;
    const int b = blockIdx.x >> 6, h = blockIdx.x & 63;
    const float* xblk = x + (size_t)b * 128 * 4096 + h * 64;

    for (int i = tid; i < 128 * 64; i += 256) {
        int c = i >> 6, w = i & 63;
        xs[i] = xblk[c * 4096 + w];
    }
    for (int i = tid; i < 128 * 128; i += 256) {
        int oc = i >> 7, c = i & 127;
        ws[c * 132 + oc] = conv_w[i];
    }
    __syncthreads();
    if (tid < 64) {
        float s = 0.f, s2 = 0.f;
#pragma unroll 8
        for (int c = 0; c < 128; c++) { float v = xs[c * 64 + tid]; s += v; s2 += v * v; }
        float m = s * 0.0078125f;
        float var = s2 * 0.0078125f - m * m;
        mu[tid] = m; rs[tid] = rsqrtf(var + 1e-5f);
    }
    __syncthreads();
    for (int i = tid; i < 128 * 64; i += 256) {
        int c = i >> 6, w = i & 63;
        xs[i] = (xs[i] - mu[w]) * rs[w] * norm_w[c] + norm_b[c];
    }
    __syncthreads();

    const int oc0 = (tid >> 4) * 8;
    const int w0 = (tid & 15) * 4;
    float4 acc[8];
#pragma unroll
    for (int i = 0; i < 8; i++) acc[i] = make_float4(0.f, 0.f, 0.f, 0.f);
#pragma unroll 4
    for (int c = 0; c < 128; c++) {
        float4 a0 = *(const float4*)(ws + c * 132 + oc0);
        float4 a1 = *(const float4*)(ws + c * 132 + oc0 + 4);
        float4 bv = *(const float4*)(xs + c * 64 + w0);
        f4fma(a0.x, bv, acc[0]); f4fma(a0.y, bv, acc[1]);
        f4fma(a0.z, bv, acc[2]); f4fma(a0.w, bv, acc[3]);
        f4fma(a1.x, bv, acc[4]); f4fma(a1.y, bv, acc[5]);
        f4fma(a1.z, bv, acc[6]); f4fma(a1.w, bv, acc[7]);
    }
#pragma unroll
    for (int i = 0; i < 8; i++) {
        float bia = conv_b[oc0 + i];
        acc[i].x = leaky(acc[i].x + bia); acc[i].y = leaky(acc[i].y + bia);
        acc[i].z = leaky(acc[i].z + bia); acc[i].w = leaky(acc[i].w + bia);
    }
    if (oc0 < 64) {
#pragma unroll
        for (int j = 0; j < 4; j++) {
            int w = w0 + j;
            float* dst = g_feat[0] + ((size_t)blockIdx.x * 64 + w) * 64 + oc0;
            *(float4*)dst = make_float4(gc(acc[0], j), gc(acc[1], j), gc(acc[2], j), gc(acc[3], j));
            *(float4*)(dst + 4) = make_float4(gc(acc[4], j), gc(acc[5], j), gc(acc[6], j), gc(acc[7], j));
        }
    } else {
#pragma unroll
        for (int j = 0; j < 4; j++) {
            int w = w0 + j;
            float* dst = g_feat[1] + ((size_t)(b * 64 + w) * 64 + h) * 64 + (oc0 - 64);
            *(float4*)dst = make_float4(gc(acc[0], j), gc(acc[1], j), gc(acc[2], j), gc(acc[3], j));
            *(float4*)(dst + 4) = make_float4(gc(acc[4], j), gc(acc[5], j), gc(acc[6], j), gc(acc[7], j));
        }
    }
}

// ============================================================================
// GCM via warp-level mma.sync bf16 3-term split.
// Block = (graph, ch-tile 32, dir). State rows r = c*8+f (256), cols = node (64).
// ============================================================================
#define OFF_AHI 0u
#define OFF_ALO 8192u
#define OFF_SHI 16384u
#define OFF_SLO 49152u
#define OFF_U   81920u
#define OFF_XS  151552u
#define OFF_WB  220160u
#define GCM_SMEM 222272u

// One adj application: Uf[r][l] = sum_m S[r][m]*adj[l][m], via 3-term bf16 split MMA.
__device__ __forceinline__ void warp_app(uint32_t smb, float* __restrict__ Uf,
                                         int wid, int lane)
{
    float c[2][8][4];
#pragma unroll
    for (int mt = 0; mt < 2; mt++)
#pragma unroll
        for (int nt = 0; nt < 8; nt++)
#pragma unroll
            for (int j = 0; j < 4; j++) c[mt][nt][j] = 0.f;

    const int warpM = wid * 32;
    const uint32_t aRow = warpM + (lane & 15);
    const uint32_t aK8 = (lane >> 4) * 8;
    const int q = lane >> 3;
    const uint32_t bRow = (lane & 7) + ((q >> 1) * 8);
    const uint32_t bK8 = (q & 1) * 8;

#pragma unroll
    for (int pass = 0; pass < 3; pass++) {
        const uint32_t aOff = (pass < 2) ? OFF_SHI : OFF_SLO;
        const uint32_t bOff = (pass == 1) ? OFF_ALO : OFF_AHI;
#pragma unroll
        for (int ks = 0; ks < 4; ks++) {
            uint32_t a0[4], a1[4];
            ldsm4(a0, smb + aOff + SW128(aRow * 128 + (ks * 16 + aK8) * 2));
            ldsm4(a1, smb + aOff + SW128((aRow + 16) * 128 + (ks * 16 + aK8) * 2));
#pragma unroll
            for (int nt2 = 0; nt2 < 4; nt2++) {
                uint32_t br[4];
                ldsm4(br, smb + bOff + SW128((nt2 * 16 + bRow) * 128 + (ks * 16 + bK8) * 2));
                mma16816(c[0][nt2 * 2 + 0], a0, br[0], br[1]);
                mma16816(c[0][nt2 * 2 + 1], a0, br[2], br[3]);
                mma16816(c[1][nt2 * 2 + 0], a1, br[0], br[1]);
                mma16816(c[1][nt2 * 2 + 1], a1, br[2], br[3]);
            }
        }
    }
    // store fragments to Uf [256][68]
    const int rg = lane >> 2, cg = (lane & 3) * 2;
#pragma unroll
    for (int mt = 0; mt < 2; mt++) {
        const int row0 = warpM + mt * 16 + rg;
#pragma unroll
        for (int nt = 0; nt < 8; nt++) {
            const int col = nt * 8 + cg;
            *(float2*)&Uf[row0 * 68 + col] = make_float2(c[mt][nt][0], c[mt][nt][1]);
            *(float2*)&Uf[(row0 + 8) * 68 + col] = make_float2(c[mt][nt][2], c[mt][nt][3]);
        }
    }
}

// Store one state row (64 fp32) as bf16 hi/lo into SW128 operand buffers.
__device__ __forceinline__ void store_row_split(char* smc, int r, const float* v) {
    const uint32_t rowb = (uint32_t)r * 128;
#pragma unroll
    for (int j = 0; j < 64; j += 8) {
        ushort hi[8], lo[8];
#pragma unroll
        for (int q = 0; q < 8; q++) {
            float x = v[j + q];
            __nv_bfloat16 h = __float2bfloat16(x);
            __nv_bfloat16 l = __float2bfloat16(x - __bfloat162float(h));
            hi[q] = *(ushort*)&h; lo[q] = *(ushort*)&l;
        }
        uint32_t o = SW128(rowb + j * 2);
        *(uint4*)(smc + OFF_SHI + o) = *(uint4*)hi;
        *(uint4*)(smc + OFF_SLO + o) = *(uint4*)lo;
    }
}

__global__ __launch_bounds__(256, 1) void k_gcm(
    const float* __restrict__ adj_h, const float* __restrict__ adj_v,
    const float* __restrict__ head_h, const float* __restrict__ tail_h,
    const float* __restrict__ w1_h, const float* __restrict__ w2_h,
    const float* __restrict__ head_v, const float* __restrict__ tail_v,
    const float* __restrict__ w1_v, const float* __restrict__ w2_v)
{
    extern __shared__ __align__(1024) char sm[];
    const uint32_t smb = smem_u32(sm);
    float* Uf = (float*)(sm + OFF_U);
    float* Xs = (float*)(sm + OFF_XS);
    float* WB = (float*)(sm + OFF_WB);
    const int tid = threadIdx.x;
    const int wid = tid >> 5, lane = tid & 31;
    const int graph = blockIdx.x, ct = blockIdx.y, dir = blockIdx.z;
    const float* adj = dir ? adj_v : adj_h;
    const float* hw = dir ? head_v : head_h;
    const float* tw = dir ? tail_v : tail_h;
    const float* w1 = dir ? w1_v : w1_h;
    const float* w2 = dir ? w2_v : w2_h;
    const float* feat = g_feat[dir] + (size_t)graph * 4096 + ct * 32;
    float* gout = g_gout[dir] + (size_t)graph * 4096 + ct * 32;

    const int r = tid;  // my state row (0..255)

    // ---- stage adj bf16 hi/lo (SW128) + weights + head scratch ----
    for (int i = tid; i < 4096; i += 256) {
        int l = i >> 6, m = i & 63;
        float v = adj[i];
        __nv_bfloat16 h = __float2bfloat16(v);
        __nv_bfloat16 lo = __float2bfloat16(v - __bfloat162float(h));
        uint32_t o = SW128((uint32_t)(l * 128 + m * 2));
        *(__nv_bfloat16*)(sm + OFF_AHI + o) = h;
        *(__nv_bfloat16*)(sm + OFF_ALO + o) = lo;
        Uf[m * 68 + l] = v;  // adjT fp32 (head use)
    }
    for (int i = tid; i < 528; i += 256) {
        float v;
        if (i < 8) v = hw[i];
        else if (i < 16) v = tw[i - 8];
        else if (i < 272) v = w1[i - 16];
        else v = w2[i - 272];
        WB[i] = v;
    }
    float* featS = Uf + 64 * 68;         // [64 m][33]
    float* gS = featS + 64 * 33;         // [64 l][33]
    for (int i = tid; i < 2048; i += 256) {
        int m = i >> 5, c = i & 31;
        featS[m * 33 + c] = feat[m * 64 + c];
    }
    __syncthreads();

    // ---- head: g = adj @ feat ----
#pragma unroll
    for (int p = 0; p < 8; p++) {
        int idx = tid + p * 256;
        int l = idx >> 5, c = idx & 31;
        float s = 0.f;
#pragma unroll 8
        for (int m = 0; m < 64; m++) s = fmaf(Uf[m * 68 + l], featS[m * 33 + c], s);
        gS[l * 33 + c] = s;
    }
    __syncthreads();

    // X[r][l] = g[l][c] * hw[f]
    {
        const int c = r >> 3, f = r & 7;
        const float hf = WB[f];
        float v[64];
#pragma unroll
        for (int l = 0; l < 64; l++) {
            float x = gS[l * 33 + c] * hf;
            v[l] = x;
            Xs[r * 67 + l] = x;
        }
        store_row_split(sm, r, v);
    }
    __syncthreads();

    // ---- ResGCN body: X += adj @ ( leaky( (adj@X) W1 ) W2 ) ----
    for (int it = 0; it < 4; it++) {
        // app1: U = S @ adj^T
        warp_app(smb, Uf, wid, lane);
        __syncthreads();

        // fmix: T = leaky(U W1) W2 -> bf16 hi/lo operand bufs
        {
            const float* W1 = WB + 16 + it * 64;
            const float* W2 = WB + 272 + it * 64;
            float vi[8][8];
            int nn[8], cc[8];
#pragma unroll
            for (int p = 0; p < 8; p++) {
                int idx = tid + p * 256;
                nn[p] = idx & 63; cc[p] = idx >> 6;
#pragma unroll
                for (int f = 0; f < 8; f++) vi[p][f] = Uf[(cc[p] * 8 + f) * 68 + nn[p]];
            }
            float4 m0[8], m1[8];
#pragma unroll
            for (int p = 0; p < 8; p++) { m0[p] = make_float4(0.f,0.f,0.f,0.f); m1[p] = m0[p]; }
#pragma unroll
            for (int fi = 0; fi < 8; fi++) {
                float4 wa = *(const float4*)(W1 + fi * 8);
                float4 wb = *(const float4*)(W1 + fi * 8 + 4);
#pragma unroll
                for (int p = 0; p < 8; p++) { f4fma(vi[p][fi], wa, m0[p]); f4fma(vi[p][fi], wb, m1[p]); }
            }
#pragma unroll
            for (int p = 0; p < 8; p++) {
                m0[p].x = leaky(m0[p].x); m0[p].y = leaky(m0[p].y);
                m0[p].z = leaky(m0[p].z); m0[p].w = leaky(m0[p].w);
                m1[p].x = leaky(m1[p].x); m1[p].y = leaky(m1[p].y);
                m1[p].z = leaky(m1[p].z); m1[p].w = leaky(m1[p].w);
            }
            float4 o0[8], o1[8];
#pragma unroll
            for (int p = 0; p < 8; p++) { o0[p] = make_float4(0.f,0.f,0.f,0.f); o1[p] = o0[p]; }
#pragma unroll
            for (int fi = 0; fi < 8; fi++) {
                float4 wa = *(const float4*)(W2 + fi * 8);
                float4 wb = *(const float4*)(W2 + fi * 8 + 4);
#pragma unroll
                for (int p = 0; p < 8; p++) {
                    float mv = (fi < 4) ? gc(m0[p], fi) : gc(m1[p], fi - 4);
                    f4fma(mv, wa, o0[p]); f4fma(mv, wb, o1[p]);
                }
            }
#pragma unroll
            for (int p = 0; p < 8; p++) {
                float ov[8] = {o0[p].x, o0[p].y, o0[p].z, o0[p].w, o1[p].x, o1[p].y, o1[p].z, o1[p].w};
#pragma unroll
                for (int f = 0; f < 8; f++) {
                    float x = ov[f];
                    __nv_bfloat16 h = __float2bfloat16(x);
                    __nv_bfloat16 l = __float2bfloat16(x - __bfloat162float(h));
                    uint32_t o = SW128((uint32_t)((cc[p] * 8 + f) * 128 + nn[p] * 2));
                    *(__nv_bfloat16*)(sm + OFF_SHI + o) = h;
                    *(__nv_bfloat16*)(sm + OFF_SLO + o) = l;
                }
            }
        }
        __syncthreads();

        // app2: R = T @ adj^T ; X += R ; re-split
        warp_app(smb, Uf, wid, lane);
        __syncthreads();
        {
            float v[64];
#pragma unroll
            for (int j = 0; j < 64; j++) {
                float x = Xs[r * 67 + j] + Uf[r * 68 + j];
                v[j] = x;
                Xs[r * 67 + j] = x;
            }
            store_row_split(sm, r, v);
        }
        __syncthreads();
    }

    // ---- tail: t[m][c] = sum_f X[(c,f)][m] * tw[f]; out = leaky(adj @ t) ----
    for (int i = tid; i < 4096; i += 256) {
        int l = i >> 6, m = i & 63;
        Uf[m * 68 + l] = adj[i];
    }
    float* tS = Uf + 64 * 68;  // [64 m][33]
    __syncthreads();
#pragma unroll
    for (int p = 0; p < 8; p++) {
        int idx = tid + p * 256;
        int m = idx & 63, c = idx >> 6;
        float s = 0.f;
#pragma unroll
        for (int f = 0; f < 8; f++) s = fmaf(Xs[(c * 8 + f) * 67 + m], WB[8 + f], s);
        tS[m * 33 + c] = s;
    }
    __syncthreads();
    {
        const int l0 = wid * 8;
        const int c = lane;
        float g8[8];
#pragma unroll
        for (int i = 0; i < 8; i++) g8[i] = 0.f;
#pragma unroll 8
        for (int m = 0; m < 64; m++) {
            float fv = tS[m * 33 + c];
            float4 a0 = *(const float4*)(Uf + m * 68 + l0);
            float4 a1 = *(const float4*)(Uf + m * 68 + l0 + 4);
            g8[0] = fmaf(a0.x, fv, g8[0]); g8[1] = fmaf(a0.y, fv, g8[1]);
            g8[2] = fmaf(a0.z, fv, g8[2]); g8[3] = fmaf(a0.w, fv, g8[3]);
            g8[4] = fmaf(a1.x, fv, g8[4]); g8[5] = fmaf(a1.y, fv, g8[5]);
            g8[6] = fmaf(a1.z, fv, g8[6]); g8[7] = fmaf(a1.w, fv, g8[7]);
        }
#pragma unroll
        for (int i = 0; i < 8; i++) gout[(l0 + i) * 64 + c] = leaky(g8[i]);
    }
}

// ============================================================================
// Kernel 3: gather + fuse 1x1 conv + bias + residual
// ============================================================================
__global__ __launch_bounds__(256) void k_fuse(
    const float* __restrict__ x, const float* __restrict__ fuse_w,
    const float* __restrict__ fuse_b, float* __restrict__ out)
{
    extern __shared__ float sm_fuse[];
    float* as = sm_fuse;
    float* ws = sm_fuse + 128 * 68;
    const int tid = threadIdx.x;
    const int b = blockIdx.x >> 6, h = blockIdx.x & 63;

    const float* gh = g_gout[0] + (size_t)blockIdx.x * 4096;
    for (int i = tid; i < 4096; i += 256) {
        int w = i >> 6, c = i & 63;
        as[c * 68 + w] = gh[i];
    }
    const float* gvbase = g_gout[1] + (size_t)b * 64 * 4096 + h * 64;
    for (int i = tid; i < 4096; i += 256) {
        int w = i >> 6, c = i & 63;
        as[(64 + c) * 68 + w] = gvbase[(size_t)w * 4096 + c];
    }
    for (int i = tid; i < 128 * 128; i += 256) {
        int oc = i >> 7, c = i & 127;
        ws[c * 132 + oc] = fuse_w[i];
    }
    __syncthreads();

    const int oc0 = (tid >> 4) * 8;
    const int w0 = (tid & 15) * 4;
    float4 acc[8];
#pragma unroll
    for (int i = 0; i < 8; i++) acc[i] = make_float4(0.f, 0.f, 0.f, 0.f);
#pragma unroll 4
    for (int c = 0; c < 128; c++) {
        float4 a0 = *(const float4*)(ws + c * 132 + oc0);
        float4 a1 = *(const float4*)(ws + c * 132 + oc0 + 4);
        float4 bv = *(const float4*)(as + c * 68 + w0);
        f4fma(a0.x, bv, acc[0]); f4fma(a0.y, bv, acc[1]);
        f4fma(a0.z, bv, acc[2]); f4fma(a0.w, bv, acc[3]);
        f4fma(a1.x, bv, acc[4]); f4fma(a1.y, bv, acc[5]);
        f4fma(a1.z, bv, acc[6]); f4fma(a1.w, bv, acc[7]);
    }
    const float* xblk = x + (size_t)b * 128 * 4096 + h * 64;
    float* oblk = out + (size_t)b * 128 * 4096 + h * 64;
#pragma unroll
    for (int i = 0; i < 8; i++) {
        int oc = oc0 + i;
        float bia = fuse_b[oc];
        float4 xv = *(const float4*)(xblk + (size_t)oc * 4096 + w0);
        *(float4*)(oblk + (size_t)oc * 4096 + w0) =
            make_float4(acc[i].x + bia + xv.x, acc[i].y + bia + xv.y,
                        acc[i].z + bia + xv.z, acc[i].w + bia + xv.w);
    }
}

extern "C" void kernel_launch(void* const* d_in, const int* in_sizes, int n_in,
                              void* d_out, int out_size)
{
    const float* x      = (const float*)d_in[0];
    const float* adj_h  = (const float*)d_in[1];
    const float* adj_v  = (const float*)d_in[2];
    const float* norm_w = (const float*)d_in[3];
    const float* norm_b = (const float*)d_in[4];
    const float* conv_w = (const float*)d_in[5];
    const float* conv_b = (const float*)d_in[6];
    const float* fuse_w = (const float*)d_in[7];
    const float* fuse_b = (const float*)d_in[8];
    const float* head_h = (const float*)d_in[9];
    const float* tail_h = (const float*)d_in[10];
    const float* w1_h   = (const float*)d_in[11];
    const float* w2_h   = (const float*)d_in[12];
    const float* head_v = (const float*)d_in[13];
    const float* tail_v = (const float*)d_in[14];
    const float* w1_v   = (const float*)d_in[15];
    const float* w2_v   = (const float*)d_in[16];
    float* out = (float*)d_out;

    const size_t s_pre  = (size_t)(128 * 64 + 128 * 132 + 128) * sizeof(float);
    const size_t s_fuse = (size_t)(128 * 68 + 128 * 132) * sizeof(float);
    cudaFuncSetAttribute(k_pre, cudaFuncAttributeMaxDynamicSharedMemorySize, (int)s_pre);
    cudaFuncSetAttribute(k_gcm, cudaFuncAttributeMaxDynamicSharedMemorySize, (int)GCM_SMEM);
    cudaFuncSetAttribute(k_fuse, cudaFuncAttributeMaxDynamicSharedMemorySize, (int)s_fuse);

    k_pre<<<256, 256, s_pre>>>(x, norm_w, norm_b, conv_w, conv_b);
    k_gcm<<<dim3(256, 2, 2), 256, GCM_SMEM>>>(adj_h, adj_v, head_h, tail_h, w1_h, w2_h,
                                              head_v, tail_v, w1_v, w2_v);
    k_fuse<<<256, 256, s_fuse>>>(x, fuse_w, fuse_b, out);
}

// round 6
// speedup vs baseline: 1.3229x; 1.0315x over previous
#include <cuda_runtime.h>
#include <cuda_bf16.h>
#include <cstdint>

#define LRELU_SLOPE 0.2f

// Scratch: [dir][graph(256)][node(64)][ch(64)]
__device__ float g_feat[2][256 * 64 * 64];
__device__ float g_gout[2][256 * 64 * 64];

__device__ __forceinline__ float leaky(float v) { return v >= 0.f ? v : LRELU_SLOPE * v; }

__device__ __forceinline__ void f4fma(float a, const float4& b, float4& c) {
    c.x = fmaf(a, b.x, c.x); c.y = fmaf(a, b.y, c.y);
    c.z = fmaf(a, b.z, c.z); c.w = fmaf(a, b.w, c.w);
}
__device__ __forceinline__ float gc(const float4& v, int j) {
    switch (j) { case 0: return v.x; case 1: return v.y; case 2: return v.z; default: return v.w; }
}

__device__ __forceinline__ uint32_t smem_u32(const void* p) {
    uint32_t a;
    asm("{ .reg .u64 t; cvta.to.shared.u64 t, %1; cvt.u32.u64 %0, t; }" : "=r"(a) : "l"(p));
    return a;
}
#define SW128(o) ((o) ^ (((o) >> 3) & 0x70))

__device__ __forceinline__ void ldsm4(uint32_t r[4], uint32_t addr) {
    asm volatile("ldmatrix.sync.aligned.m8n8.x4.shared.b16 {%0,%1,%2,%3}, [%4];"
                 : "=r"(r[0]), "=r"(r[1]), "=r"(r[2]), "=r"(r[3]) : "r"(addr));
}
__device__ __forceinline__ void mma16816(float c[4], const uint32_t a[4], uint32_t b0, uint32_t b1) {
    asm volatile(
        "mma.sync.aligned.m16n8k16.row.col.f32.bf16.bf16.f32 "
        "{%0,%1,%2,%3}, {%4,%5,%6,%7}, {%8,%9}, {%0,%1,%2,%3};"
        : "+f"(c[0]), "+f"(c[1]), "+f"(c[2]), "+f"(c[3])
        : "r"(a[0]), "r"(a[1]), "r"(a[2]), "r"(a[3]), "r"(b0), "r"(b1));
}

// ============================================================================
// Kernel 1: LayerNorm + 1x1 conv + leaky + strip split
// ============================================================================
__global__ __launch_bounds__(256) void k_pre(
    const float* __restrict__ x, const float* __restrict__ norm_w,
    const float* __restrict__ norm_b, const float* __restrict__ conv_w,
    const float* __restrict__ conv_b)
{
    extern __shared__ float sm_pre[];
    float* xs = sm_pre;
    float* ws = sm_pre + 128 * 64;
    float* mu = ws + 128 * 132;
    float* rs = mu + 64;
    const int tid = threadIdx.x;
    const int b = blockIdx.x >> 6, h = blockIdx.x & 63;
    const float* xblk = x + (size_t)b * 128 * 4096 + h * 64;

    for (int i = tid; i < 128 * 64; i += 256) {
        int c = i >> 6, w = i & 63;
        xs[i] = xblk[c * 4096 + w];
    }
    for (int i = tid; i < 128 * 128; i += 256) {
        int oc = i >> 7, c = i & 127;
        ws[c * 132 + oc] = conv_w[i];
    }
    __syncthreads();
    if (tid < 64) {
        float s = 0.f, s2 = 0.f;
#pragma unroll 8
        for (int c = 0; c < 128; c++) { float v = xs[c * 64 + tid]; s += v; s2 += v * v; }
        float m = s * 0.0078125f;
        float var = s2 * 0.0078125f - m * m;
        mu[tid] = m; rs[tid] = rsqrtf(var + 1e-5f);
    }
    __syncthreads();
    for (int i = tid; i < 128 * 64; i += 256) {
        int c = i >> 6, w = i & 63;
        xs[i] = (xs[i] - mu[w]) * rs[w] * norm_w[c] + norm_b[c];
    }
    __syncthreads();

    const int oc0 = (tid >> 4) * 8;
    const int w0 = (tid & 15) * 4;
    float4 acc[8];
#pragma unroll
    for (int i = 0; i < 8; i++) acc[i] = make_float4(0.f, 0.f, 0.f, 0.f);
#pragma unroll 4
    for (int c = 0; c < 128; c++) {
        float4 a0 = *(const float4*)(ws + c * 132 + oc0);
        float4 a1 = *(const float4*)(ws + c * 132 + oc0 + 4);
        float4 bv = *(const float4*)(xs + c * 64 + w0);
        f4fma(a0.x, bv, acc[0]); f4fma(a0.y, bv, acc[1]);
        f4fma(a0.z, bv, acc[2]); f4fma(a0.w, bv, acc[3]);
        f4fma(a1.x, bv, acc[4]); f4fma(a1.y, bv, acc[5]);
        f4fma(a1.z, bv, acc[6]); f4fma(a1.w, bv, acc[7]);
    }
#pragma unroll
    for (int i = 0; i < 8; i++) {
        float bia = conv_b[oc0 + i];
        acc[i].x = leaky(acc[i].x + bia); acc[i].y = leaky(acc[i].y + bia);
        acc[i].z = leaky(acc[i].z + bia); acc[i].w = leaky(acc[i].w + bia);
    }
    if (oc0 < 64) {
#pragma unroll
        for (int j = 0; j < 4; j++) {
            int w = w0 + j;
            float* dst = g_feat[0] + ((size_t)blockIdx.x * 64 + w) * 64 + oc0;
            *(float4*)dst = make_float4(gc(acc[0], j), gc(acc[1], j), gc(acc[2], j), gc(acc[3], j));
            *(float4*)(dst + 4) = make_float4(gc(acc[4], j), gc(acc[5], j), gc(acc[6], j), gc(acc[7], j));
        }
    } else {
#pragma unroll
        for (int j = 0; j < 4; j++) {
            int w = w0 + j;
            float* dst = g_feat[1] + ((size_t)(b * 64 + w) * 64 + h) * 64 + (oc0 - 64);
            *(float4*)dst = make_float4(gc(acc[0], j), gc(acc[1], j), gc(acc[2], j), gc(acc[3], j));
            *(float4*)(dst + 4) = make_float4(gc(acc[4], j), gc(acc[5], j), gc(acc[6], j), gc(acc[7], j));
        }
    }
}

// ============================================================================
// GCM via warp-level mma.sync bf16 3-term split.
// Block = (graph, ch-tile 32, dir). State rows r = c*8+f (256), cols = node (64).
// X lives ONLY as hi/lo bf16 split (XHI/XLO); T (fmix output) in THI/TLO.
// Smem (bytes):
//   AHI 0       (8 KB)  adj bf16 hi  [64 x 128B] SW128  (B operand)
//   ALO 8192    (8 KB)  adj bf16 lo
//   XHI 16384   (32 KB) X hi [256 x 128B] SW128         (A operand, app1)
//   XLO 49152   (32 KB) X lo
//   THI 81920   (32 KB) T hi                            (A operand, app2)
//   TLO 114688  (32 KB) T lo
//   U   147456  fp32 staging [256][68] (also head/tail scratch)
//   WB  217088  weights (528 floats)
// ============================================================================
#define OFF_AHI 0u
#define OFF_ALO 8192u
#define OFF_XHI 16384u
#define OFF_XLO 49152u
#define OFF_THI 81920u
#define OFF_TLO 114688u
#define OFF_U   147456u
#define OFF_WB  217088u
#define GCM_SMEM 219200u

// One adj application: acc[r][l] = sum_m S[r][m]*adj[l][m], 3-term bf16 split.
// A operand from (aHiOff/aLoOff). Epilogue RESID: X += acc in-place on XHI/XLO.
// Epilogue !RESID: store acc to Uf [256][68].
template <bool RESID>
__device__ __forceinline__ void warp_app(uint32_t smb, char* smc, float* __restrict__ Uf,
                                         uint32_t aHiOff, uint32_t aLoOff,
                                         int wid, int lane)
{
    float c[2][8][4];
#pragma unroll
    for (int mt = 0; mt < 2; mt++)
#pragma unroll
        for (int nt = 0; nt < 8; nt++)
#pragma unroll
            for (int j = 0; j < 4; j++) c[mt][nt][j] = 0.f;

    const int warpM = wid * 32;
    const uint32_t aRow = warpM + (lane & 15);
    const uint32_t aK8 = (lane >> 4) * 8;
    const int q = lane >> 3;
    const uint32_t bRow = (lane & 7) + ((q >> 1) * 8);
    const uint32_t bK8 = (q & 1) * 8;

#pragma unroll
    for (int ks = 0; ks < 4; ks++) {
        const uint32_t ao0 = SW128(aRow * 128 + (ks * 16 + aK8) * 2);
        const uint32_t ao1 = SW128((aRow + 16) * 128 + (ks * 16 + aK8) * 2);
        uint32_t aH0[4], aH1[4], aL0[4], aL1[4];
        ldsm4(aH0, smb + aHiOff + ao0);
        ldsm4(aH1, smb + aHiOff + ao1);
        ldsm4(aL0, smb + aLoOff + ao0);
        ldsm4(aL1, smb + aLoOff + ao1);
#pragma unroll
        for (int nt2 = 0; nt2 < 4; nt2++) {
            const uint32_t bo = SW128((nt2 * 16 + bRow) * 128 + (ks * 16 + bK8) * 2);
            uint32_t bH[4], bL[4];
            ldsm4(bH, smb + OFF_AHI + bo);
            ldsm4(bL, smb + OFF_ALO + bo);
            mma16816(c[0][nt2 * 2 + 0], aH0, bH[0], bH[1]);
            mma16816(c[0][nt2 * 2 + 1], aH0, bH[2], bH[3]);
            mma16816(c[1][nt2 * 2 + 0], aH1, bH[0], bH[1]);
            mma16816(c[1][nt2 * 2 + 1], aH1, bH[2], bH[3]);
            mma16816(c[0][nt2 * 2 + 0], aH0, bL[0], bL[1]);
            mma16816(c[0][nt2 * 2 + 1], aH0, bL[2], bL[3]);
            mma16816(c[1][nt2 * 2 + 0], aH1, bL[0], bL[1]);
            mma16816(c[1][nt2 * 2 + 1], aH1, bL[2], bL[3]);
            mma16816(c[0][nt2 * 2 + 0], aL0, bH[0], bH[1]);
            mma16816(c[0][nt2 * 2 + 1], aL0, bH[2], bH[3]);
            mma16816(c[1][nt2 * 2 + 0], aL1, bH[0], bH[1]);
            mma16816(c[1][nt2 * 2 + 1], aL1, bH[2], bH[3]);
        }
    }

    const int rg = lane >> 2, cg = (lane & 3) * 2;
    if (!RESID) {
#pragma unroll
        for (int mt = 0; mt < 2; mt++) {
            const int row0 = warpM + mt * 16 + rg;
#pragma unroll
            for (int nt = 0; nt < 8; nt++) {
                const int col = nt * 8 + cg;
                *(float2*)&Uf[row0 * 68 + col] = make_float2(c[mt][nt][0], c[mt][nt][1]);
                *(float2*)&Uf[(row0 + 8) * 68 + col] = make_float2(c[mt][nt][2], c[mt][nt][3]);
            }
        }
    } else {
        // X += acc in place (hi/lo reconstruct, re-split)
#pragma unroll
        for (int mt = 0; mt < 2; mt++) {
#pragma unroll
            for (int nt = 0; nt < 8; nt++) {
                const int col = nt * 8 + cg;
#pragma unroll
                for (int hh = 0; hh < 2; hh++) {
                    const int row = warpM + mt * 16 + rg + hh * 8;
                    const uint32_t off = SW128((uint32_t)(row * 128 + col * 2));
                    __nv_bfloat162 h2 = *(__nv_bfloat162*)(smc + OFF_XHI + off);
                    __nv_bfloat162 l2 = *(__nv_bfloat162*)(smc + OFF_XLO + off);
                    float x0 = __bfloat162float(h2.x) + __bfloat162float(l2.x) + c[mt][nt][hh * 2];
                    float x1 = __bfloat162float(h2.y) + __bfloat162float(l2.y) + c[mt][nt][hh * 2 + 1];
                    __nv_bfloat16 nh0 = __float2bfloat16(x0);
                    __nv_bfloat16 nl0 = __float2bfloat16(x0 - __bfloat162float(nh0));
                    __nv_bfloat16 nh1 = __float2bfloat16(x1);
                    __nv_bfloat16 nl1 = __float2bfloat16(x1 - __bfloat162float(nh1));
                    __nv_bfloat162 oh; oh.x = nh0; oh.y = nh1;
                    __nv_bfloat162 ol; ol.x = nl0; ol.y = nl1;
                    *(__nv_bfloat162*)(smc + OFF_XHI + off) = oh;
                    *(__nv_bfloat162*)(smc + OFF_XLO + off) = ol;
                }
            }
        }
    }
}

// Store one state row (64 fp32) as bf16 hi/lo into SW128 buffers at hiOff/loOff.
__device__ __forceinline__ void store_row_split(char* smc, uint32_t hiOff, uint32_t loOff,
                                                int r, const float* v) {
    const uint32_t rowb = (uint32_t)r * 128;
#pragma unroll
    for (int j = 0; j < 64; j += 8) {
        ushort hi[8], lo[8];
#pragma unroll
        for (int qq = 0; qq < 8; qq++) {
            float x = v[j + qq];
            __nv_bfloat16 h = __float2bfloat16(x);
            __nv_bfloat16 l = __float2bfloat16(x - __bfloat162float(h));
            hi[qq] = *(ushort*)&h; lo[qq] = *(ushort*)&l;
        }
        uint32_t o = SW128(rowb + j * 2);
        *(uint4*)(smc + hiOff + o) = *(uint4*)hi;
        *(uint4*)(smc + loOff + o) = *(uint4*)lo;
    }
}

__global__ __launch_bounds__(256, 1) void k_gcm(
    const float* __restrict__ adj_h, const float* __restrict__ adj_v,
    const float* __restrict__ head_h, const float* __restrict__ tail_h,
    const float* __restrict__ w1_h, const float* __restrict__ w2_h,
    const float* __restrict__ head_v, const float* __restrict__ tail_v,
    const float* __restrict__ w1_v, const float* __restrict__ w2_v)
{
    extern __shared__ __align__(1024) char sm[];
    const uint32_t smb = smem_u32(sm);
    float* Uf = (float*)(sm + OFF_U);
    float* WB = (float*)(sm + OFF_WB);
    const int tid = threadIdx.x;
    const int wid = tid >> 5, lane = tid & 31;
    const int graph = blockIdx.x, ct = blockIdx.y, dir = blockIdx.z;
    const float* adj = dir ? adj_v : adj_h;
    const float* hw = dir ? head_v : head_h;
    const float* tw = dir ? tail_v : tail_h;
    const float* w1 = dir ? w1_v : w1_h;
    const float* w2 = dir ? w2_v : w2_h;
    const float* feat = g_feat[dir] + (size_t)graph * 4096 + ct * 32;
    float* gout = g_gout[dir] + (size_t)graph * 4096 + ct * 32;

    const int r = tid;  // my state row (0..255)

    // ---- stage adj bf16 hi/lo (SW128) + weights + head scratch ----
    for (int i = tid; i < 4096; i += 256) {
        int l = i >> 6, m = i & 63;
        float v = adj[i];
        __nv_bfloat16 h = __float2bfloat16(v);
        __nv_bfloat16 lo = __float2bfloat16(v - __bfloat162float(h));
        uint32_t o = SW128((uint32_t)(l * 128 + m * 2));
        *(__nv_bfloat16*)(sm + OFF_AHI + o) = h;
        *(__nv_bfloat16*)(sm + OFF_ALO + o) = lo;
        Uf[m * 68 + l] = v;  // adjT fp32 (head use)
    }
    for (int i = tid; i < 528; i += 256) {
        float v;
        if (i < 8) v = hw[i];
        else if (i < 16) v = tw[i - 8];
        else if (i < 272) v = w1[i - 16];
        else v = w2[i - 272];
        WB[i] = v;
    }
    float* featS = Uf + 64 * 68;         // [64 m][33]
    float* gS = featS + 64 * 33;         // [64 l][33]
    for (int i = tid; i < 2048; i += 256) {
        int m = i >> 5, c = i & 31;
        featS[m * 33 + c] = feat[m * 64 + c];
    }
    __syncthreads();

    // ---- head: g = adj @ feat ----
#pragma unroll
    for (int p = 0; p < 8; p++) {
        int idx = tid + p * 256;
        int l = idx >> 5, c = idx & 31;
        float s = 0.f;
#pragma unroll 8
        for (int m = 0; m < 64; m++) s = fmaf(Uf[m * 68 + l], featS[m * 33 + c], s);
        gS[l * 33 + c] = s;
    }
    __syncthreads();

    // X[r][l] = g[l][c] * hw[f]  -> XHI/XLO only
    {
        const int c = r >> 3, f = r & 7;
        const float hf = WB[f];
        float v[64];
#pragma unroll
        for (int l = 0; l < 64; l++) v[l] = gS[l * 33 + c] * hf;
        store_row_split(sm, OFF_XHI, OFF_XLO, r, v);
    }
    __syncthreads();

    // ---- ResGCN body: X += adj @ ( leaky( (adj@X) W1 ) W2 ) ----
    for (int it = 0; it < 4; it++) {
        // app1: U = X @ adj^T -> Uf
        warp_app<false>(smb, sm, Uf, OFF_XHI, OFF_XLO, wid, lane);
        __syncthreads();

        // fmix: T = leaky(U W1) W2 -> THI/TLO
        {
            const float* W1 = WB + 16 + it * 64;
            const float* W2 = WB + 272 + it * 64;
            float vi[8][8];
            int nn[8], cc[8];
#pragma unroll
            for (int p = 0; p < 8; p++) {
                int idx = tid + p * 256;
                nn[p] = idx & 63; cc[p] = idx >> 6;
#pragma unroll
                for (int f = 0; f < 8; f++) vi[p][f] = Uf[(cc[p] * 8 + f) * 68 + nn[p]];
            }
            float4 m0[8], m1[8];
#pragma unroll
            for (int p = 0; p < 8; p++) { m0[p] = make_float4(0.f,0.f,0.f,0.f); m1[p] = m0[p]; }
#pragma unroll
            for (int fi = 0; fi < 8; fi++) {
                float4 wa = *(const float4*)(W1 + fi * 8);
                float4 wb = *(const float4*)(W1 + fi * 8 + 4);
#pragma unroll
                for (int p = 0; p < 8; p++) { f4fma(vi[p][fi], wa, m0[p]); f4fma(vi[p][fi], wb, m1[p]); }
            }
#pragma unroll
            for (int p = 0; p < 8; p++) {
                m0[p].x = leaky(m0[p].x); m0[p].y = leaky(m0[p].y);
                m0[p].z = leaky(m0[p].z); m0[p].w = leaky(m0[p].w);
                m1[p].x = leaky(m1[p].x); m1[p].y = leaky(m1[p].y);
                m1[p].z = leaky(m1[p].z); m1[p].w = leaky(m1[p].w);
            }
            float4 o0[8], o1[8];
#pragma unroll
            for (int p = 0; p < 8; p++) { o0[p] = make_float4(0.f,0.f,0.f,0.f); o1[p] = o0[p]; }
#pragma unroll
            for (int fi = 0; fi < 8; fi++) {
                float4 wa = *(const float4*)(W2 + fi * 8);
                float4 wb = *(const float4*)(W2 + fi * 8 + 4);
#pragma unroll
                for (int p = 0; p < 8; p++) {
                    float mv = (fi < 4) ? gc(m0[p], fi) : gc(m1[p], fi - 4);
                    f4fma(mv, wa, o0[p]); f4fma(mv, wb, o1[p]);
                }
            }
#pragma unroll
            for (int p = 0; p < 8; p++) {
                float ov[8] = {o0[p].x, o0[p].y, o0[p].z, o0[p].w, o1[p].x, o1[p].y, o1[p].z, o1[p].w};
#pragma unroll
                for (int f = 0; f < 8; f++) {
                    float x = ov[f];
                    __nv_bfloat16 h = __float2bfloat16(x);
                    __nv_bfloat16 l = __float2bfloat16(x - __bfloat162float(h));
                    uint32_t o = SW128((uint32_t)((cc[p] * 8 + f) * 128 + nn[p] * 2));
                    *(__nv_bfloat16*)(sm + OFF_THI + o) = h;
                    *(__nv_bfloat16*)(sm + OFF_TLO + o) = l;
                }
            }
        }
        __syncthreads();

        // app2: R = T @ adj^T ; X += R in place (fragment-direct)
        warp_app<true>(smb, sm, Uf, OFF_THI, OFF_TLO, wid, lane);
        __syncwarp();
    }
    __syncthreads();

    // ---- tail: t[m][c] = sum_f X[(c,f)][m] * tw[f]; out = leaky(adj @ t) ----
    for (int i = tid; i < 4096; i += 256) {
        int l = i >> 6, m = i & 63;
        Uf[m * 68 + l] = adj[i];
    }
    float* tS = Uf + 64 * 68;  // [64 m][33]
    __syncthreads();
#pragma unroll
    for (int p = 0; p < 8; p++) {
        int idx = tid + p * 256;
        int m = idx & 63, c = idx >> 6;
        float s = 0.f;
#pragma unroll
        for (int f = 0; f < 8; f++) {
            uint32_t off = SW128((uint32_t)((c * 8 + f) * 128 + m * 2));
            float xv = __bfloat162float(*(__nv_bfloat16*)(sm + OFF_XHI + off))
                     + __bfloat162float(*(__nv_bfloat16*)(sm + OFF_XLO + off));
            s = fmaf(xv, WB[8 + f], s);
        }
        tS[m * 33 + c] = s;
    }
    __syncthreads();
    {
        const int l0 = wid * 8;
        const int c = lane;
        float g8[8];
#pragma unroll
        for (int i = 0; i < 8; i++) g8[i] = 0.f;
#pragma unroll 8
        for (int m = 0; m < 64; m++) {
            float fv = tS[m * 33 + c];
            float4 a0 = *(const float4*)(Uf + m * 68 + l0);
            float4 a1 = *(const float4*)(Uf + m * 68 + l0 + 4);
            g8[0] = fmaf(a0.x, fv, g8[0]); g8[1] = fmaf(a0.y, fv, g8[1]);
            g8[2] = fmaf(a0.z, fv, g8[2]); g8[3] = fmaf(a0.w, fv, g8[3]);
            g8[4] = fmaf(a1.x, fv, g8[4]); g8[5] = fmaf(a1.y, fv, g8[5]);
            g8[6] = fmaf(a1.z, fv, g8[6]); g8[7] = fmaf(a1.w, fv, g8[7]);
        }
#pragma unroll
        for (int i = 0; i < 8; i++) gout[(l0 + i) * 64 + c] = leaky(g8[i]);
    }
}

// ============================================================================
// Kernel 3: gather + fuse 1x1 conv + bias + residual
// ============================================================================
__global__ __launch_bounds__(256) void k_fuse(
    const float* __restrict__ x, const float* __restrict__ fuse_w,
    const float* __restrict__ fuse_b, float* __restrict__ out)
{
    extern __shared__ float sm_fuse[];
    float* as = sm_fuse;
    float* ws = sm_fuse + 128 * 68;
    const int tid = threadIdx.x;
    const int b = blockIdx.x >> 6, h = blockIdx.x & 63;

    const float* gh = g_gout[0] + (size_t)blockIdx.x * 4096;
    for (int i = tid; i < 4096; i += 256) {
        int w = i >> 6, c = i & 63;
        as[c * 68 + w] = gh[i];
    }
    const float* gvbase = g_gout[1] + (size_t)b * 64 * 4096 + h * 64;
    for (int i = tid; i < 4096; i += 256) {
        int w = i >> 6, c = i & 63;
        as[(64 + c) * 68 + w] = gvbase[(size_t)w * 4096 + c];
    }
    for (int i = tid; i < 128 * 128; i += 256) {
        int oc = i >> 7, c = i & 127;
        ws[c * 132 + oc] = fuse_w[i];
    }
    __syncthreads();

    const int oc0 = (tid >> 4) * 8;
    const int w0 = (tid & 15) * 4;
    float4 acc[8];
#pragma unroll
    for (int i = 0; i < 8; i++) acc[i] = make_float4(0.f, 0.f, 0.f, 0.f);
#pragma unroll 4
    for (int c = 0; c < 128; c++) {
        float4 a0 = *(const float4*)(ws + c * 132 + oc0);
        float4 a1 = *(const float4*)(ws + c * 132 + oc0 + 4);
        float4 bv = *(const float4*)(as + c * 68 + w0);
        f4fma(a0.x, bv, acc[0]); f4fma(a0.y, bv, acc[1]);
        f4fma(a0.z, bv, acc[2]); f4fma(a0.w, bv, acc[3]);
        f4fma(a1.x, bv, acc[4]); f4fma(a1.y, bv, acc[5]);
        f4fma(a1.z, bv, acc[6]); f4fma(a1.w, bv, acc[7]);
    }
    const float* xblk = x + (size_t)b * 128 * 4096 + h * 64;
    float* oblk = out + (size_t)b * 128 * 4096 + h * 64;
#pragma unroll
    for (int i = 0; i < 8; i++) {
        int oc = oc0 + i;
        float bia = fuse_b[oc];
        float4 xv = *(const float4*)(xblk + (size_t)oc * 4096 + w0);
        *(float4*)(oblk + (size_t)oc * 4096 + w0) =
            make_float4(acc[i].x + bia + xv.x, acc[i].y + bia + xv.y,
                        acc[i].z + bia + xv.z, acc[i].w + bia + xv.w);
    }
}

extern "C" void kernel_launch(void* const* d_in, const int* in_sizes, int n_in,
                              void* d_out, int out_size)
{
    const float* x      = (const float*)d_in[0];
    const float* adj_h  = (const float*)d_in[1];
    const float* adj_v  = (const float*)d_in[2];
    const float* norm_w = (const float*)d_in[3];
    const float* norm_b = (const float*)d_in[4];
    const float* conv_w = (const float*)d_in[5];
    const float* conv_b = (const float*)d_in[6];
    const float* fuse_w = (const float*)d_in[7];
    const float* fuse_b = (const float*)d_in[8];
    const float* head_h = (const float*)d_in[9];
    const float* tail_h = (const float*)d_in[10];
    const float* w1_h   = (const float*)d_in[11];
    const float* w2_h   = (const float*)d_in[12];
    const float* head_v = (const float*)d_in[13];
    const float* tail_v = (const float*)d_in[14];
    const float* w1_v   = (const float*)d_in[15];
    const float* w2_v   = (const float*)d_in[16];
    float* out = (float*)d_out;

    const size_t s_pre  = (size_t)(128 * 64 + 128 * 132 + 128) * sizeof(float);
    const size_t s_fuse = (size_t)(128 * 68 + 128 * 132) * sizeof(float);
    cudaFuncSetAttribute(k_pre, cudaFuncAttributeMaxDynamicSharedMemorySize, (int)s_pre);
    cudaFuncSetAttribute(k_gcm, cudaFuncAttributeMaxDynamicSharedMemorySize, (int)GCM_SMEM);
    cudaFuncSetAttribute(k_fuse, cudaFuncAttributeMaxDynamicSharedMemorySize, (int)s_fuse);

    k_pre<<<256, 256, s_pre>>>(x, norm_w, norm_b, conv_w, conv_b);
    k_gcm<<<dim3(256, 2, 2), 256, GCM_SMEM>>>(adj_h, adj_v, head_h, tail_h, w1_h, w2_h,
                                              head_v, tail_v, w1_v, w2_v);
    k_fuse<<<256, 256, s_fuse>>>(x, fuse_w, fuse_b, out);
}

// round 7
// speedup vs baseline: 1.5631x; 1.1816x over previous
#include <cuda_runtime.h>
#include <cuda_bf16.h>
#include <cstdint>

#define LRELU_SLOPE 0.2f

// Scratch: [dir][graph(256)][node(64)][ch(64)]
__device__ float g_feat[2][256 * 64 * 64];
__device__ float g_gout[2][256 * 64 * 64];

__device__ __forceinline__ float leaky(float v) { return v >= 0.f ? v : LRELU_SLOPE * v; }

__device__ __forceinline__ void f4fma(float a, const float4& b, float4& c) {
    c.x = fmaf(a, b.x, c.x); c.y = fmaf(a, b.y, c.y);
    c.z = fmaf(a, b.z, c.z); c.w = fmaf(a, b.w, c.w);
}
__device__ __forceinline__ float gc(const float4& v, int j) {
    switch (j) { case 0: return v.x; case 1: return v.y; case 2: return v.z; default: return v.w; }
}

__device__ __forceinline__ uint32_t smem_u32(const void* p) {
    uint32_t a;
    asm("{ .reg .u64 t; cvta.to.shared.u64 t, %1; cvt.u32.u64 %0, t; }" : "=r"(a) : "l"(p));
    return a;
}
#define SW128(o) ((o) ^ (((o) >> 3) & 0x70))

__device__ __forceinline__ void ldsm4(uint32_t r[4], uint32_t addr) {
    asm volatile("ldmatrix.sync.aligned.m8n8.x4.shared.b16 {%0,%1,%2,%3}, [%4];"
                 : "=r"(r[0]), "=r"(r[1]), "=r"(r[2]), "=r"(r[3]) : "r"(addr));
}
__device__ __forceinline__ void mma16816(float c[4], const uint32_t a[4], uint32_t b0, uint32_t b1) {
    asm volatile(
        "mma.sync.aligned.m16n8k16.row.col.f32.bf16.bf16.f32 "
        "{%0,%1,%2,%3}, {%4,%5,%6,%7}, {%8,%9}, {%0,%1,%2,%3};"
        : "+f"(c[0]), "+f"(c[1]), "+f"(c[2]), "+f"(c[3])
        : "r"(a[0]), "r"(a[1]), "r"(a[2]), "r"(a[3]), "r"(b0), "r"(b1));
}

// ============================================================================
// Kernel 1: LayerNorm + 1x1 conv + leaky + strip split
// ============================================================================
__global__ __launch_bounds__(256) void k_pre(
    const float* __restrict__ x, const float* __restrict__ norm_w,
    const float* __restrict__ norm_b, const float* __restrict__ conv_w,
    const float* __restrict__ conv_b)
{
    extern __shared__ float sm_pre[];
    float* xs = sm_pre;
    float* ws = sm_pre + 128 * 64;
    float* mu = ws + 128 * 132;
    float* rs = mu + 64;
    const int tid = threadIdx.x;
    const int b = blockIdx.x >> 6, h = blockIdx.x & 63;
    const float* xblk = x + (size_t)b * 128 * 4096 + h * 64;

    for (int i = tid; i < 128 * 64; i += 256) {
        int c = i >> 6, w = i & 63;
        xs[i] = xblk[c * 4096 + w];
    }
    for (int i = tid; i < 128 * 128; i += 256) {
        int oc = i >> 7, c = i & 127;
        ws[c * 132 + oc] = conv_w[i];
    }
    __syncthreads();
    if (tid < 64) {
        float s = 0.f, s2 = 0.f;
#pragma unroll 8
        for (int c = 0; c < 128; c++) { float v = xs[c * 64 + tid]; s += v; s2 += v * v; }
        float m = s * 0.0078125f;
        float var = s2 * 0.0078125f - m * m;
        mu[tid] = m; rs[tid] = rsqrtf(var + 1e-5f);
    }
    __syncthreads();
    for (int i = tid; i < 128 * 64; i += 256) {
        int c = i >> 6, w = i & 63;
        xs[i] = (xs[i] - mu[w]) * rs[w] * norm_w[c] + norm_b[c];
    }
    __syncthreads();

    const int oc0 = (tid >> 4) * 8;
    const int w0 = (tid & 15) * 4;
    float4 acc[8];
#pragma unroll
    for (int i = 0; i < 8; i++) acc[i] = make_float4(0.f, 0.f, 0.f, 0.f);
#pragma unroll 4
    for (int c = 0; c < 128; c++) {
        float4 a0 = *(const float4*)(ws + c * 132 + oc0);
        float4 a1 = *(const float4*)(ws + c * 132 + oc0 + 4);
        float4 bv = *(const float4*)(xs + c * 64 + w0);
        f4fma(a0.x, bv, acc[0]); f4fma(a0.y, bv, acc[1]);
        f4fma(a0.z, bv, acc[2]); f4fma(a0.w, bv, acc[3]);
        f4fma(a1.x, bv, acc[4]); f4fma(a1.y, bv, acc[5]);
        f4fma(a1.z, bv, acc[6]); f4fma(a1.w, bv, acc[7]);
    }
#pragma unroll
    for (int i = 0; i < 8; i++) {
        float bia = conv_b[oc0 + i];
        acc[i].x = leaky(acc[i].x + bia); acc[i].y = leaky(acc[i].y + bia);
        acc[i].z = leaky(acc[i].z + bia); acc[i].w = leaky(acc[i].w + bia);
    }
    if (oc0 < 64) {
#pragma unroll
        for (int j = 0; j < 4; j++) {
            int w = w0 + j;
            float* dst = g_feat[0] + ((size_t)blockIdx.x * 64 + w) * 64 + oc0;
            *(float4*)dst = make_float4(gc(acc[0], j), gc(acc[1], j), gc(acc[2], j), gc(acc[3], j));
            *(float4*)(dst + 4) = make_float4(gc(acc[4], j), gc(acc[5], j), gc(acc[6], j), gc(acc[7], j));
        }
    } else {
#pragma unroll
        for (int j = 0; j < 4; j++) {
            int w = w0 + j;
            float* dst = g_feat[1] + ((size_t)(b * 64 + w) * 64 + h) * 64 + (oc0 - 64);
            *(float4*)dst = make_float4(gc(acc[0], j), gc(acc[1], j), gc(acc[2], j), gc(acc[3], j));
            *(float4*)(dst + 4) = make_float4(gc(acc[4], j), gc(acc[5], j), gc(acc[6], j), gc(acc[7], j));
        }
    }
}

// ============================================================================
// GCM via warp-level mma.sync bf16 3-term split. CH-TILE = 16 -> 2 CTAs/SM.
// Block = (graph, ch-tile 16, dir). State rows r = c*8+f (128), cols = node (64).
// Smem (bytes):
//   AHI 0      (8 KB)  adj bf16 hi [64 x 128B] SW128 (B operand)
//   ALO 8192   (8 KB)  adj bf16 lo
//   XHI 16384  (16 KB) X hi [128 x 128B] SW128       (A operand, app1)
//   XLO 32768  (16 KB) X lo
//   THI 49152  (16 KB) T hi (A operand, app2)   } aliased with Uf fp32 [128][68]
//   TLO 65536  (16 KB) T lo                     } (=34816 B @49152)
//   WB  83968  weights (528 floats)
// Total 86080 -> 2 CTAs/SM.
// ============================================================================
#define OFF_AHI 0u
#define OFF_ALO 8192u
#define OFF_XHI 16384u
#define OFF_XLO 32768u
#define OFF_THI 49152u
#define OFF_TLO 65536u
#define OFF_U   49152u
#define OFF_WB  83968u
#define GCM_SMEM 86080u

// One adj application: acc[r][l] = sum_m S[r][m]*adj[l][m], 3-term bf16 split.
// RESID: X += acc in place on XHI/XLO. !RESID: store acc to Uf [128][68].
template <bool RESID>
__device__ __forceinline__ void warp_app(uint32_t smb, char* smc, float* __restrict__ Uf,
                                         uint32_t aHiOff, uint32_t aLoOff,
                                         int wid, int lane)
{
    float c[8][4];
#pragma unroll
    for (int nt = 0; nt < 8; nt++)
#pragma unroll
        for (int j = 0; j < 4; j++) c[nt][j] = 0.f;

    const int warpM = wid * 16;
    const uint32_t aRow = warpM + (lane & 15);
    const uint32_t aK8 = (lane >> 4) * 8;
    const int q = lane >> 3;
    const uint32_t bRow = (lane & 7) + ((q >> 1) * 8);
    const uint32_t bK8 = (q & 1) * 8;

#pragma unroll
    for (int ks = 0; ks < 4; ks++) {
        const uint32_t ao = SW128(aRow * 128 + (ks * 16 + aK8) * 2);
        uint32_t aH[4], aL[4];
        ldsm4(aH, smb + aHiOff + ao);
        ldsm4(aL, smb + aLoOff + ao);
#pragma unroll
        for (int nt2 = 0; nt2 < 4; nt2++) {
            const uint32_t bo = SW128((nt2 * 16 + bRow) * 128 + (ks * 16 + bK8) * 2);
            uint32_t bH[4], bL[4];
            ldsm4(bH, smb + OFF_AHI + bo);
            ldsm4(bL, smb + OFF_ALO + bo);
            mma16816(c[nt2 * 2 + 0], aH, bH[0], bH[1]);
            mma16816(c[nt2 * 2 + 1], aH, bH[2], bH[3]);
            mma16816(c[nt2 * 2 + 0], aH, bL[0], bL[1]);
            mma16816(c[nt2 * 2 + 1], aH, bL[2], bL[3]);
            mma16816(c[nt2 * 2 + 0], aL, bH[0], bH[1]);
            mma16816(c[nt2 * 2 + 1], aL, bH[2], bH[3]);
        }
    }

    const int rg = lane >> 2, cg = (lane & 3) * 2;
    if (!RESID) {
#pragma unroll
        for (int nt = 0; nt < 8; nt++) {
            const int col = nt * 8 + cg;
            const int row0 = warpM + rg;
            *(float2*)&Uf[row0 * 68 + col] = make_float2(c[nt][0], c[nt][1]);
            *(float2*)&Uf[(row0 + 8) * 68 + col] = make_float2(c[nt][2], c[nt][3]);
        }
    } else {
#pragma unroll
        for (int nt = 0; nt < 8; nt++) {
            const int col = nt * 8 + cg;
#pragma unroll
            for (int hh = 0; hh < 2; hh++) {
                const int row = warpM + rg + hh * 8;
                const uint32_t off = SW128((uint32_t)(row * 128 + col * 2));
                __nv_bfloat162 h2 = *(__nv_bfloat162*)(smc + OFF_XHI + off);
                __nv_bfloat162 l2 = *(__nv_bfloat162*)(smc + OFF_XLO + off);
                float x0 = __bfloat162float(h2.x) + __bfloat162float(l2.x) + c[nt][hh * 2];
                float x1 = __bfloat162float(h2.y) + __bfloat162float(l2.y) + c[nt][hh * 2 + 1];
                __nv_bfloat16 nh0 = __float2bfloat16(x0);
                __nv_bfloat16 nl0 = __float2bfloat16(x0 - __bfloat162float(nh0));
                __nv_bfloat16 nh1 = __float2bfloat16(x1);
                __nv_bfloat16 nl1 = __float2bfloat16(x1 - __bfloat162float(nh1));
                __nv_bfloat162 oh; oh.x = nh0; oh.y = nh1;
                __nv_bfloat162 ol; ol.x = nl0; ol.y = nl1;
                *(__nv_bfloat162*)(smc + OFF_XHI + off) = oh;
                *(__nv_bfloat162*)(smc + OFF_XLO + off) = ol;
            }
        }
    }
}

// Store one row's 32-col slab (fp32 v[32]) as bf16 hi/lo at cols [cb, cb+32).
__device__ __forceinline__ void store_row_split32(char* smc, uint32_t hiOff, uint32_t loOff,
                                                  int r, int cb, const float* v) {
    const uint32_t rowb = (uint32_t)r * 128;
#pragma unroll
    for (int j = 0; j < 32; j += 8) {
        ushort hi[8], lo[8];
#pragma unroll
        for (int qq = 0; qq < 8; qq++) {
            float x = v[j + qq];
            __nv_bfloat16 h = __float2bfloat16(x);
            __nv_bfloat16 l = __float2bfloat16(x - __bfloat162float(h));
            hi[qq] = *(ushort*)&h; lo[qq] = *(ushort*)&l;
        }
        uint32_t o = SW128(rowb + (cb + j) * 2);
        *(uint4*)(smc + hiOff + o) = *(uint4*)hi;
        *(uint4*)(smc + loOff + o) = *(uint4*)lo;
    }
}

__global__ __launch_bounds__(256, 2) void k_gcm(
    const float* __restrict__ adj_h, const float* __restrict__ adj_v,
    const float* __restrict__ head_h, const float* __restrict__ tail_h,
    const float* __restrict__ w1_h, const float* __restrict__ w2_h,
    const float* __restrict__ head_v, const float* __restrict__ tail_v,
    const float* __restrict__ w1_v, const float* __restrict__ w2_v)
{
    extern __shared__ __align__(1024) char sm[];
    const uint32_t smb = smem_u32(sm);
    float* Uf = (float*)(sm + OFF_U);     // [128][68] fp32 (aliases THI/TLO)
    float* WB = (float*)(sm + OFF_WB);
    const int tid = threadIdx.x;
    const int wid = tid >> 5, lane = tid & 31;
    const int graph = blockIdx.x, ct = blockIdx.y, dir = blockIdx.z;
    const float* adj = dir ? adj_v : adj_h;
    const float* hw = dir ? head_v : head_h;
    const float* tw = dir ? tail_v : tail_h;
    const float* w1 = dir ? w1_v : w1_h;
    const float* w2 = dir ? w2_v : w2_h;
    const float* feat = g_feat[dir] + (size_t)graph * 4096 + ct * 16;
    float* gout = g_gout[dir] + (size_t)graph * 4096 + ct * 16;

    // ---- stage adj bf16 hi/lo (SW128) + weights + head scratch ----
    for (int i = tid; i < 4096; i += 256) {
        int l = i >> 6, m = i & 63;
        float v = adj[i];
        __nv_bfloat16 h = __float2bfloat16(v);
        __nv_bfloat16 lo = __float2bfloat16(v - __bfloat162float(h));
        uint32_t o = SW128((uint32_t)(l * 128 + m * 2));
        *(__nv_bfloat16*)(sm + OFF_AHI + o) = h;
        *(__nv_bfloat16*)(sm + OFF_ALO + o) = lo;
        Uf[m * 68 + l] = v;  // adjT fp32 (head use)
    }
    for (int i = tid; i < 528; i += 256) {
        float v;
        if (i < 8) v = hw[i];
        else if (i < 16) v = tw[i - 8];
        else if (i < 272) v = w1[i - 16];
        else v = w2[i - 272];
        WB[i] = v;
    }
    float* featS = Uf + 64 * 68;          // [64 m][17]
    float* gS = featS + 64 * 17;          // [64 l][17]
    for (int i = tid; i < 1024; i += 256) {
        int m = i >> 4, c = i & 15;
        featS[m * 17 + c] = feat[m * 64 + c];
    }
    __syncthreads();

    // ---- head: g[l][c] = (adj @ feat)[l][c] ----
#pragma unroll
    for (int p = 0; p < 4; p++) {
        int idx = tid + p * 256;
        int l = idx >> 4, c = idx & 15;
        float s = 0.f;
#pragma unroll 8
        for (int m = 0; m < 64; m++) s = fmaf(Uf[m * 68 + l], featS[m * 17 + c], s);
        gS[l * 17 + c] = s;
    }
    __syncthreads();

    // X[r][l] = g[l][c] * hw[f]  -> XHI/XLO (each thread: half a row)
    {
        const int r = tid >> 1, half = tid & 1;
        const int c = r >> 3, f = r & 7;
        const float hf = WB[f];
        const int cb = half * 32;
        float v[32];
#pragma unroll
        for (int l = 0; l < 32; l++) v[l] = gS[(cb + l) * 17 + c] * hf;
        store_row_split32(sm, OFF_XHI, OFF_XLO, r, cb, v);
    }
    __syncthreads();

    // ---- ResGCN body: X += adj @ ( leaky( (adj@X) W1 ) W2 ) ----
    for (int it = 0; it < 4; it++) {
        // app1: U = X @ adj^T -> Uf
        warp_app<false>(smb, sm, Uf, OFF_XHI, OFF_XLO, wid, lane);
        __syncthreads();

        // fmix: T = leaky(U W1) W2 -> THI/TLO (aliased w/ Uf: gather, sync, write)
        {
            const float* W1 = WB + 16 + it * 64;
            const float* W2 = WB + 272 + it * 64;
            float vi[4][8];
            int nn[4], cc[4];
#pragma unroll
            for (int p = 0; p < 4; p++) {
                int idx = tid + p * 256;
                nn[p] = idx & 63; cc[p] = idx >> 6;
#pragma unroll
                for (int f = 0; f < 8; f++) vi[p][f] = Uf[(cc[p] * 8 + f) * 68 + nn[p]];
            }
            __syncthreads();  // all reads of Uf done before T writes clobber it
            float4 m0[4], m1[4];
#pragma unroll
            for (int p = 0; p < 4; p++) { m0[p] = make_float4(0.f,0.f,0.f,0.f); m1[p] = m0[p]; }
#pragma unroll
            for (int fi = 0; fi < 8; fi++) {
                float4 wa = *(const float4*)(W1 + fi * 8);
                float4 wb = *(const float4*)(W1 + fi * 8 + 4);
#pragma unroll
                for (int p = 0; p < 4; p++) { f4fma(vi[p][fi], wa, m0[p]); f4fma(vi[p][fi], wb, m1[p]); }
            }
#pragma unroll
            for (int p = 0; p < 4; p++) {
                m0[p].x = leaky(m0[p].x); m0[p].y = leaky(m0[p].y);
                m0[p].z = leaky(m0[p].z); m0[p].w = leaky(m0[p].w);
                m1[p].x = leaky(m1[p].x); m1[p].y = leaky(m1[p].y);
                m1[p].z = leaky(m1[p].z); m1[p].w = leaky(m1[p].w);
            }
            float4 o0[4], o1[4];
#pragma unroll
            for (int p = 0; p < 4; p++) { o0[p] = make_float4(0.f,0.f,0.f,0.f); o1[p] = o0[p]; }
#pragma unroll
            for (int fi = 0; fi < 8; fi++) {
                float4 wa = *(const float4*)(W2 + fi * 8);
                float4 wb = *(const float4*)(W2 + fi * 8 + 4);
#pragma unroll
                for (int p = 0; p < 4; p++) {
                    float mv = (fi < 4) ? gc(m0[p], fi) : gc(m1[p], fi - 4);
                    f4fma(mv, wa, o0[p]); f4fma(mv, wb, o1[p]);
                }
            }
#pragma unroll
            for (int p = 0; p < 4; p++) {
                float ov[8] = {o0[p].x, o0[p].y, o0[p].z, o0[p].w, o1[p].x, o1[p].y, o1[p].z, o1[p].w};
#pragma unroll
                for (int f = 0; f < 8; f++) {
                    float x = ov[f];
                    __nv_bfloat16 h = __float2bfloat16(x);
                    __nv_bfloat16 l = __float2bfloat16(x - __bfloat162float(h));
                    uint32_t o = SW128((uint32_t)((cc[p] * 8 + f) * 128 + nn[p] * 2));
                    *(__nv_bfloat16*)(sm + OFF_THI + o) = h;
                    *(__nv_bfloat16*)(sm + OFF_TLO + o) = l;
                }
            }
        }
        __syncthreads();

        // app2: R = T @ adj^T ; X += R in place (fragment-direct, warp-local rows)
        warp_app<true>(smb, sm, Uf, OFF_THI, OFF_TLO, wid, lane);
        __syncwarp();
    }
    __syncthreads();

    // ---- tail: t[m][c] = sum_f X[(c,f)][m]*tw[f]; out = leaky(adj @ t) ----
    for (int i = tid; i < 4096; i += 256) {
        int l = i >> 6, m = i & 63;
        Uf[m * 68 + l] = adj[i];  // clobbers T (consumed)
    }
    float* tS = Uf + 64 * 68;  // [64 m][17]
    __syncthreads();
#pragma unroll
    for (int p = 0; p < 4; p++) {
        int idx = tid + p * 256;
        int m = idx & 63, c = idx >> 6;
        float s = 0.f;
#pragma unroll
        for (int f = 0; f < 8; f++) {
            uint32_t off = SW128((uint32_t)((c * 8 + f) * 128 + m * 2));
            float xv = __bfloat162float(*(__nv_bfloat16*)(sm + OFF_XHI + off))
                     + __bfloat162float(*(__nv_bfloat16*)(sm + OFF_XLO + off));
            s = fmaf(xv, WB[8 + f], s);
        }
        tS[m * 17 + c] = s;
    }
    __syncthreads();
    {
        const int l0 = wid * 8 + (lane >> 4) * 4;
        const int c = lane & 15;
        float g4[4] = {0.f, 0.f, 0.f, 0.f};
#pragma unroll 8
        for (int m = 0; m < 64; m++) {
            float fv = tS[m * 17 + c];
            float4 a = *(const float4*)(Uf + m * 68 + l0);
            g4[0] = fmaf(a.x, fv, g4[0]); g4[1] = fmaf(a.y, fv, g4[1]);
            g4[2] = fmaf(a.z, fv, g4[2]); g4[3] = fmaf(a.w, fv, g4[3]);
        }
#pragma unroll
        for (int i = 0; i < 4; i++) gout[(l0 + i) * 64 + c] = leaky(g4[i]);
    }
}

// ============================================================================
// Kernel 3: gather + fuse 1x1 conv + bias + residual
// ============================================================================
__global__ __launch_bounds__(256) void k_fuse(
    const float* __restrict__ x, const float* __restrict__ fuse_w,
    const float* __restrict__ fuse_b, float* __restrict__ out)
{
    extern __shared__ float sm_fuse[];
    float* as = sm_fuse;
    float* ws = sm_fuse + 128 * 68;
    const int tid = threadIdx.x;
    const int b = blockIdx.x >> 6, h = blockIdx.x & 63;

    const float* gh = g_gout[0] + (size_t)blockIdx.x * 4096;
    for (int i = tid; i < 4096; i += 256) {
        int w = i >> 6, c = i & 63;
        as[c * 68 + w] = gh[i];
    }
    const float* gvbase = g_gout[1] + (size_t)b * 64 * 4096 + h * 64;
    for (int i = tid; i < 4096; i += 256) {
        int w = i >> 6, c = i & 63;
        as[(64 + c) * 68 + w] = gvbase[(size_t)w * 4096 + c];
    }
    for (int i = tid; i < 128 * 128; i += 256) {
        int oc = i >> 7, c = i & 127;
        ws[c * 132 + oc] = fuse_w[i];
    }
    __syncthreads();

    const int oc0 = (tid >> 4) * 8;
    const int w0 = (tid & 15) * 4;
    float4 acc[8];
#pragma unroll
    for (int i = 0; i < 8; i++) acc[i] = make_float4(0.f, 0.f, 0.f, 0.f);
#pragma unroll 4
    for (int c = 0; c < 128; c++) {
        float4 a0 = *(const float4*)(ws + c * 132 + oc0);
        float4 a1 = *(const float4*)(ws + c * 132 + oc0 + 4);
        float4 bv = *(const float4*)(as + c * 68 + w0);
        f4fma(a0.x, bv, acc[0]); f4fma(a0.y, bv, acc[1]);
        f4fma(a0.z, bv, acc[2]); f4fma(a0.w, bv, acc[3]);
        f4fma(a1.x, bv, acc[4]); f4fma(a1.y, bv, acc[5]);
        f4fma(a1.z, bv, acc[6]); f4fma(a1.w, bv, acc[7]);
    }
    const float* xblk = x + (size_t)b * 128 * 4096 + h * 64;
    float* oblk = out + (size_t)b * 128 * 4096 + h * 64;
#pragma unroll
    for (int i = 0; i < 8; i++) {
        int oc = oc0 + i;
        float bia = fuse_b[oc];
        float4 xv = *(const float4*)(xblk + (size_t)oc * 4096 + w0);
        *(float4*)(oblk + (size_t)oc * 4096 + w0) =
            make_float4(acc[i].x + bia + xv.x, acc[i].y + bia + xv.y,
                        acc[i].z + bia + xv.z, acc[i].w + bia + xv.w);
    }
}

extern "C" void kernel_launch(void* const* d_in, const int* in_sizes, int n_in,
                              void* d_out, int out_size)
{
    const float* x      = (const float*)d_in[0];
    const float* adj_h  = (const float*)d_in[1];
    const float* adj_v  = (const float*)d_in[2];
    const float* norm_w = (const float*)d_in[3];
    const float* norm_b = (const float*)d_in[4];
    const float* conv_w = (const float*)d_in[5];
    const float* conv_b = (const float*)d_in[6];
    const float* fuse_w = (const float*)d_in[7];
    const float* fuse_b = (const float*)d_in[8];
    const float* head_h = (const float*)d_in[9];
    const float* tail_h = (const float*)d_in[10];
    const float* w1_h   = (const float*)d_in[11];
    const float* w2_h   = (const float*)d_in[12];
    const float* head_v = (const float*)d_in[13];
    const float* tail_v = (const float*)d_in[14];
    const float* w1_v   = (const float*)d_in[15];
    const float* w2_v   = (const float*)d_in[16];
    float* out = (float*)d_out;

    const size_t s_pre  = (size_t)(128 * 64 + 128 * 132 + 128) * sizeof(float);
    const size_t s_fuse = (size_t)(128 * 68 + 128 * 132) * sizeof(float);
    cudaFuncSetAttribute(k_pre, cudaFuncAttributeMaxDynamicSharedMemorySize, (int)s_pre);
    cudaFuncSetAttribute(k_gcm, cudaFuncAttributeMaxDynamicSharedMemorySize, (int)GCM_SMEM);
    cudaFuncSetAttribute(k_fuse, cudaFuncAttributeMaxDynamicSharedMemorySize, (int)s_fuse);

    k_pre<<<256, 256, s_pre>>>(x, norm_w, norm_b, conv_w, conv_b);
    k_gcm<<<dim3(256, 4, 2), 256, GCM_SMEM>>>(adj_h, adj_v, head_h, tail_h, w1_h, w2_h,
                                              head_v, tail_v, w1_v, w2_v);
    k_fuse<<<256, 256, s_fuse>>>(x, fuse_w, fuse_b, out);
}

// round 8
// speedup vs baseline: 1.5731x; 1.0064x over previous
#include <cuda_runtime.h>
#include <cuda_bf16.h>
#include <cstdint>

#define LRELU_SLOPE 0.2f

// Scratch: [dir][graph(256)][node(64)][ch(64)]
__device__ float g_feat[2][256 * 64 * 64];
__device__ float g_gout[2][256 * 64 * 64];

__device__ __forceinline__ float leaky(float v) { return v >= 0.f ? v : LRELU_SLOPE * v; }

__device__ __forceinline__ void f4fma(float a, const float4& b, float4& c) {
    c.x = fmaf(a, b.x, c.x); c.y = fmaf(a, b.y, c.y);
    c.z = fmaf(a, b.z, c.z); c.w = fmaf(a, b.w, c.w);
}

// ---- packed f32x2 helpers (sm_100 FFMA2 pipe) ----
__device__ __forceinline__ uint64_t pk2(float x, float y) {
    uint64_t r; asm("mov.b64 %0, {%1, %2};" : "=l"(r) : "f"(x), "f"(y)); return r;
}
__device__ __forceinline__ void upk2(uint64_t v, float& x, float& y) {
    asm("mov.b64 {%0, %1}, %2;" : "=f"(x), "=f"(y) : "l"(v));
}
__device__ __forceinline__ uint64_t fma2(uint64_t a, uint64_t b, uint64_t c) {
    uint64_t d; asm("fma.rn.f32x2 %0, %1, %2, %3;" : "=l"(d) : "l"(a), "l"(b), "l"(c)); return d;
}

__device__ __forceinline__ uint32_t smem_u32(const void* p) {
    uint32_t a;
    asm("{ .reg .u64 t; cvta.to.shared.u64 t, %1; cvt.u32.u64 %0, t; }" : "=r"(a) : "l"(p));
    return a;
}
#define SW128(o) ((o) ^ (((o) >> 3) & 0x70))

__device__ __forceinline__ void ldsm4(uint32_t r[4], uint32_t addr) {
    asm volatile("ldmatrix.sync.aligned.m8n8.x4.shared.b16 {%0,%1,%2,%3}, [%4];"
                 : "=r"(r[0]), "=r"(r[1]), "=r"(r[2]), "=r"(r[3]) : "r"(addr));
}
__device__ __forceinline__ void mma16816(float c[4], const uint32_t a[4], uint32_t b0, uint32_t b1) {
    asm volatile(
        "mma.sync.aligned.m16n8k16.row.col.f32.bf16.bf16.f32 "
        "{%0,%1,%2,%3}, {%4,%5,%6,%7}, {%8,%9}, {%0,%1,%2,%3};"
        : "+f"(c[0]), "+f"(c[1]), "+f"(c[2]), "+f"(c[3])
        : "r"(a[0]), "r"(a[1]), "r"(a[2]), "r"(a[3]), "r"(b0), "r"(b1));
}

// ============================================================================
// Kernel 1: LayerNorm + 1x1 conv + leaky + strip split (FFMA2 GEMM loop)
// ============================================================================
__global__ __launch_bounds__(256) void k_pre(
    const float* __restrict__ x, const float* __restrict__ norm_w,
    const float* __restrict__ norm_b, const float* __restrict__ conv_w,
    const float* __restrict__ conv_b)
{
    extern __shared__ float sm_pre[];
    float* xs = sm_pre;
    float* ws = sm_pre + 128 * 64;
    float* mu = ws + 128 * 132;
    float* rs = mu + 64;
    const int tid = threadIdx.x;
    const int b = blockIdx.x >> 6, h = blockIdx.x & 63;
    const float* xblk = x + (size_t)b * 128 * 4096 + h * 64;

    for (int i = tid; i < 128 * 64; i += 256) {
        int c = i >> 6, w = i & 63;
        xs[i] = xblk[c * 4096 + w];
    }
    for (int i = tid; i < 128 * 128; i += 256) {
        int oc = i >> 7, c = i & 127;
        ws[c * 132 + oc] = conv_w[i];
    }
    __syncthreads();
    if (tid < 64) {
        float s = 0.f, s2 = 0.f;
#pragma unroll 8
        for (int c = 0; c < 128; c++) { float v = xs[c * 64 + tid]; s += v; s2 += v * v; }
        float m = s * 0.0078125f;
        float var = s2 * 0.0078125f - m * m;
        mu[tid] = m; rs[tid] = rsqrtf(var + 1e-5f);
    }
    __syncthreads();
    for (int i = tid; i < 128 * 64; i += 256) {
        int c = i >> 6, w = i & 63;
        xs[i] = (xs[i] - mu[w]) * rs[w] * norm_w[c] + norm_b[c];
    }
    __syncthreads();

    const int oc0 = (tid >> 4) * 8;
    const int w0 = (tid & 15) * 4;
    uint64_t acc2[16];
#pragma unroll
    for (int i = 0; i < 16; i++) acc2[i] = 0ull;
#pragma unroll 4
    for (int c = 0; c < 128; c++) {
        float4 a0 = *(const float4*)(ws + c * 132 + oc0);
        float4 a1 = *(const float4*)(ws + c * 132 + oc0 + 4);
        ulonglong2 bv = *(const ulonglong2*)(xs + c * 64 + w0);
        uint64_t d;
        d = pk2(a0.x, a0.x); acc2[0]  = fma2(d, bv.x, acc2[0]);  acc2[1]  = fma2(d, bv.y, acc2[1]);
        d = pk2(a0.y, a0.y); acc2[2]  = fma2(d, bv.x, acc2[2]);  acc2[3]  = fma2(d, bv.y, acc2[3]);
        d = pk2(a0.z, a0.z); acc2[4]  = fma2(d, bv.x, acc2[4]);  acc2[5]  = fma2(d, bv.y, acc2[5]);
        d = pk2(a0.w, a0.w); acc2[6]  = fma2(d, bv.x, acc2[6]);  acc2[7]  = fma2(d, bv.y, acc2[7]);
        d = pk2(a1.x, a1.x); acc2[8]  = fma2(d, bv.x, acc2[8]);  acc2[9]  = fma2(d, bv.y, acc2[9]);
        d = pk2(a1.y, a1.y); acc2[10] = fma2(d, bv.x, acc2[10]); acc2[11] = fma2(d, bv.y, acc2[11]);
        d = pk2(a1.z, a1.z); acc2[12] = fma2(d, bv.x, acc2[12]); acc2[13] = fma2(d, bv.y, acc2[13]);
        d = pk2(a1.w, a1.w); acc2[14] = fma2(d, bv.x, acc2[14]); acc2[15] = fma2(d, bv.y, acc2[15]);
    }
    float av[8][4];
#pragma unroll
    for (int i = 0; i < 8; i++) {
        upk2(acc2[2 * i], av[i][0], av[i][1]);
        upk2(acc2[2 * i + 1], av[i][2], av[i][3]);
        float bia = conv_b[oc0 + i];
#pragma unroll
        for (int j = 0; j < 4; j++) av[i][j] = leaky(av[i][j] + bia);
    }
    if (oc0 < 64) {
#pragma unroll
        for (int j = 0; j < 4; j++) {
            int w = w0 + j;
            float* dst = g_feat[0] + ((size_t)blockIdx.x * 64 + w) * 64 + oc0;
            *(float4*)dst = make_float4(av[0][j], av[1][j], av[2][j], av[3][j]);
            *(float4*)(dst + 4) = make_float4(av[4][j], av[5][j], av[6][j], av[7][j]);
        }
    } else {
#pragma unroll
        for (int j = 0; j < 4; j++) {
            int w = w0 + j;
            float* dst = g_feat[1] + ((size_t)(b * 64 + w) * 64 + h) * 64 + (oc0 - 64);
            *(float4*)dst = make_float4(av[0][j], av[1][j], av[2][j], av[3][j]);
            *(float4*)(dst + 4) = make_float4(av[4][j], av[5][j], av[6][j], av[7][j]);
        }
    }
}

// ============================================================================
// GCM via warp-level mma.sync bf16 3-term split. CH-TILE = 16, 2 CTAs/SM.
// Smem:
//   AHI 0 / ALO 8192 (8 KB each)      adj bf16 hi/lo (B operand)
//   XHI 16384 / XLO 32768 (16 KB)     X hi/lo (A operand app1)
//   THI 49152 / TLO 65536 (16 KB)     T hi/lo (A operand app2), aliases Uf fp32 [128][68]
//   WB  83968  scalar weights (528 f)
//   W2B 86080  duplicated-pair weight table {w,w} [it][W1|W2][fi][f'] (4 KB)
// ============================================================================
#define OFF_AHI 0u
#define OFF_ALO 8192u
#define OFF_XHI 16384u
#define OFF_XLO 32768u
#define OFF_THI 49152u
#define OFF_TLO 65536u
#define OFF_U   49152u
#define OFF_WB  83968u
#define OFF_W2B 86080u
#define GCM_SMEM 90176u

template <bool RESID>
__device__ __forceinline__ void warp_app(uint32_t smb, char* smc, float* __restrict__ Uf,
                                         uint32_t aHiOff, uint32_t aLoOff,
                                         int wid, int lane)
{
    float c[8][4];
#pragma unroll
    for (int nt = 0; nt < 8; nt++)
#pragma unroll
        for (int j = 0; j < 4; j++) c[nt][j] = 0.f;

    const int warpM = wid * 16;
    const uint32_t aRow = warpM + (lane & 15);
    const uint32_t aK8 = (lane >> 4) * 8;
    const int q = lane >> 3;
    const uint32_t bRow = (lane & 7) + ((q >> 1) * 8);
    const uint32_t bK8 = (q & 1) * 8;

#pragma unroll
    for (int ks = 0; ks < 4; ks++) {
        const uint32_t ao = SW128(aRow * 128 + (ks * 16 + aK8) * 2);
        uint32_t aH[4], aL[4];
        ldsm4(aH, smb + aHiOff + ao);
        ldsm4(aL, smb + aLoOff + ao);
#pragma unroll
        for (int nt2 = 0; nt2 < 4; nt2++) {
            const uint32_t bo = SW128((nt2 * 16 + bRow) * 128 + (ks * 16 + bK8) * 2);
            uint32_t bH[4], bL[4];
            ldsm4(bH, smb + OFF_AHI + bo);
            ldsm4(bL, smb + OFF_ALO + bo);
            mma16816(c[nt2 * 2 + 0], aH, bH[0], bH[1]);
            mma16816(c[nt2 * 2 + 1], aH, bH[2], bH[3]);
            mma16816(c[nt2 * 2 + 0], aH, bL[0], bL[1]);
            mma16816(c[nt2 * 2 + 1], aH, bL[2], bL[3]);
            mma16816(c[nt2 * 2 + 0], aL, bH[0], bH[1]);
            mma16816(c[nt2 * 2 + 1], aL, bH[2], bH[3]);
        }
    }

    const int rg = lane >> 2, cg = (lane & 3) * 2;
    if (!RESID) {
#pragma unroll
        for (int nt = 0; nt < 8; nt++) {
            const int col = nt * 8 + cg;
            const int row0 = warpM + rg;
            *(float2*)&Uf[row0 * 68 + col] = make_float2(c[nt][0], c[nt][1]);
            *(float2*)&Uf[(row0 + 8) * 68 + col] = make_float2(c[nt][2], c[nt][3]);
        }
    } else {
#pragma unroll
        for (int nt = 0; nt < 8; nt++) {
            const int col = nt * 8 + cg;
#pragma unroll
            for (int hh = 0; hh < 2; hh++) {
                const int row = warpM + rg + hh * 8;
                const uint32_t off = SW128((uint32_t)(row * 128 + col * 2));
                __nv_bfloat162 h2 = *(__nv_bfloat162*)(smc + OFF_XHI + off);
                __nv_bfloat162 l2 = *(__nv_bfloat162*)(smc + OFF_XLO + off);
                float x0 = __bfloat162float(h2.x) + __bfloat162float(l2.x) + c[nt][hh * 2];
                float x1 = __bfloat162float(h2.y) + __bfloat162float(l2.y) + c[nt][hh * 2 + 1];
                __nv_bfloat16 nh0 = __float2bfloat16(x0);
                __nv_bfloat16 nl0 = __float2bfloat16(x0 - __bfloat162float(nh0));
                __nv_bfloat16 nh1 = __float2bfloat16(x1);
                __nv_bfloat16 nl1 = __float2bfloat16(x1 - __bfloat162float(nh1));
                __nv_bfloat162 oh; oh.x = nh0; oh.y = nh1;
                __nv_bfloat162 ol; ol.x = nl0; ol.y = nl1;
                *(__nv_bfloat162*)(smc + OFF_XHI + off) = oh;
                *(__nv_bfloat162*)(smc + OFF_XLO + off) = ol;
            }
        }
    }
}

__device__ __forceinline__ void store_row_split32(char* smc, uint32_t hiOff, uint32_t loOff,
                                                  int r, int cb, const float* v) {
    const uint32_t rowb = (uint32_t)r * 128;
#pragma unroll
    for (int j = 0; j < 32; j += 8) {
        ushort hi[8], lo[8];
#pragma unroll
        for (int qq = 0; qq < 8; qq++) {
            float x = v[j + qq];
            __nv_bfloat16 h = __float2bfloat16(x);
            __nv_bfloat16 l = __float2bfloat16(x - __bfloat162float(h));
            hi[qq] = *(ushort*)&h; lo[qq] = *(ushort*)&l;
        }
        uint32_t o = SW128(rowb + (cb + j) * 2);
        *(uint4*)(smc + hiOff + o) = *(uint4*)hi;
        *(uint4*)(smc + loOff + o) = *(uint4*)lo;
    }
}

__global__ __launch_bounds__(256, 2) void k_gcm(
    const float* __restrict__ adj_h, const float* __restrict__ adj_v,
    const float* __restrict__ head_h, const float* __restrict__ tail_h,
    const float* __restrict__ w1_h, const float* __restrict__ w2_h,
    const float* __restrict__ head_v, const float* __restrict__ tail_v,
    const float* __restrict__ w1_v, const float* __restrict__ w2_v)
{
    extern __shared__ __align__(1024) char sm[];
    const uint32_t smb = smem_u32(sm);
    float* Uf = (float*)(sm + OFF_U);     // [128][68] fp32 (aliases THI/TLO)
    float* WB = (float*)(sm + OFF_WB);
    const int tid = threadIdx.x;
    const int wid = tid >> 5, lane = tid & 31;
    const int graph = blockIdx.x, ct = blockIdx.y, dir = blockIdx.z;
    const float* adj = dir ? adj_v : adj_h;
    const float* hw = dir ? head_v : head_h;
    const float* tw = dir ? tail_v : tail_h;
    const float* w1 = dir ? w1_v : w1_h;
    const float* w2 = dir ? w2_v : w2_h;
    const float* feat = g_feat[dir] + (size_t)graph * 4096 + ct * 16;
    float* gout = g_gout[dir] + (size_t)graph * 4096 + ct * 16;

    // ---- stage adj bf16 hi/lo + weights + dup-pair weight table ----
    for (int i = tid; i < 4096; i += 256) {
        int l = i >> 6, m = i & 63;
        float v = adj[i];
        __nv_bfloat16 h = __float2bfloat16(v);
        __nv_bfloat16 lo = __float2bfloat16(v - __bfloat162float(h));
        uint32_t o = SW128((uint32_t)(l * 128 + m * 2));
        *(__nv_bfloat16*)(sm + OFF_AHI + o) = h;
        *(__nv_bfloat16*)(sm + OFF_ALO + o) = lo;
        Uf[m * 68 + l] = v;  // adjT fp32 (head use)
    }
    for (int i = tid; i < 528; i += 256) {
        float v;
        if (i < 8) v = hw[i];
        else if (i < 16) v = tw[i - 8];
        else if (i < 272) v = w1[i - 16];
        else v = w2[i - 272];
        WB[i] = v;
    }
    // WB2: [it][0=W1,1=W2][fi][f'] duplicated pairs, from global (no extra sync)
    for (int i = tid; i < 512; i += 256) {
        int it = i >> 7, rest = i & 127;
        int s = rest >> 6, idx = rest & 63;
        float v = s ? w2[it * 64 + idx] : w1[it * 64 + idx];
        *(float2*)(sm + OFF_W2B + (size_t)i * 8) = make_float2(v, v);
    }
    float* featS = Uf + 64 * 68;          // [64 m][17]
    float* gS = featS + 64 * 17;          // [64 l][17]
    for (int i = tid; i < 1024; i += 256) {
        int m = i >> 4, c = i & 15;
        featS[m * 17 + c] = feat[m * 64 + c];
    }
    __syncthreads();

    // ---- head: g[l][c] = (adj @ feat)[l][c] ----
#pragma unroll
    for (int p = 0; p < 4; p++) {
        int idx = tid + p * 256;
        int l = idx >> 4, c = idx & 15;
        float s = 0.f;
#pragma unroll 8
        for (int m = 0; m < 64; m++) s = fmaf(Uf[m * 68 + l], featS[m * 17 + c], s);
        gS[l * 17 + c] = s;
    }
    __syncthreads();

    // X[r][l] = g[l][c] * hw[f]  -> XHI/XLO
    {
        const int r = tid >> 1, half = tid & 1;
        const int c = r >> 3, f = r & 7;
        const float hf = WB[f];
        const int cb = half * 32;
        float v[32];
#pragma unroll
        for (int l = 0; l < 32; l++) v[l] = gS[(cb + l) * 17 + c] * hf;
        store_row_split32(sm, OFF_XHI, OFF_XLO, r, cb, v);
    }
    __syncthreads();

    const int nn = tid & 63;
    const int c0 = tid >> 6;  // cc[p] = c0 + p*4

    // ---- ResGCN body ----
    for (int it = 0; it < 4; it++) {
        // app1: U = X @ adj^T -> Uf
        warp_app<false>(smb, sm, Uf, OFF_XHI, OFF_XLO, wid, lane);
        __syncthreads();

        // fmix: T = leaky(U W1) W2 -> THI/TLO  (packed f32x2, channel-pairs)
        {
            float vi[4][8];
#pragma unroll
            for (int p = 0; p < 4; p++) {
                int cc = c0 + p * 4;
#pragma unroll
                for (int f = 0; f < 8; f++) vi[p][f] = Uf[(cc * 8 + f) * 68 + nn];
            }
            __syncthreads();  // Uf reads done before T writes (alias)

            uint64_t V[2][8];
#pragma unroll
            for (int qq = 0; qq < 2; qq++)
#pragma unroll
                for (int f = 0; f < 8; f++) V[qq][f] = pk2(vi[2 * qq][f], vi[2 * qq + 1][f]);

            const char* wbase = sm + OFF_W2B + it * 1024;
            uint64_t m2[2][8];
#pragma unroll
            for (int qq = 0; qq < 2; qq++)
#pragma unroll
                for (int f = 0; f < 8; f++) m2[qq][f] = 0ull;
#pragma unroll
            for (int fi = 0; fi < 8; fi++) {
                const char* wr = wbase + fi * 64;
                ulonglong2 wa = *(const ulonglong2*)(wr);
                ulonglong2 wb = *(const ulonglong2*)(wr + 16);
                ulonglong2 wc = *(const ulonglong2*)(wr + 32);
                ulonglong2 wd = *(const ulonglong2*)(wr + 48);
#pragma unroll
                for (int qq = 0; qq < 2; qq++) {
                    m2[qq][0] = fma2(V[qq][fi], wa.x, m2[qq][0]);
                    m2[qq][1] = fma2(V[qq][fi], wa.y, m2[qq][1]);
                    m2[qq][2] = fma2(V[qq][fi], wb.x, m2[qq][2]);
                    m2[qq][3] = fma2(V[qq][fi], wb.y, m2[qq][3]);
                    m2[qq][4] = fma2(V[qq][fi], wc.x, m2[qq][4]);
                    m2[qq][5] = fma2(V[qq][fi], wc.y, m2[qq][5]);
                    m2[qq][6] = fma2(V[qq][fi], wd.x, m2[qq][6]);
                    m2[qq][7] = fma2(V[qq][fi], wd.y, m2[qq][7]);
                }
            }
            // leaky (scalar unpack/repack)
#pragma unroll
            for (int qq = 0; qq < 2; qq++)
#pragma unroll
                for (int f = 0; f < 8; f++) {
                    float a, b2;
                    upk2(m2[qq][f], a, b2);
                    m2[qq][f] = pk2(leaky(a), leaky(b2));
                }
            // stage 2
            const char* wbase2 = wbase + 512;
            uint64_t o2[2][8];
#pragma unroll
            for (int qq = 0; qq < 2; qq++)
#pragma unroll
                for (int f = 0; f < 8; f++) o2[qq][f] = 0ull;
#pragma unroll
            for (int fi = 0; fi < 8; fi++) {
                const char* wr = wbase2 + fi * 64;
                ulonglong2 wa = *(const ulonglong2*)(wr);
                ulonglong2 wb = *(const ulonglong2*)(wr + 16);
                ulonglong2 wc = *(const ulonglong2*)(wr + 32);
                ulonglong2 wd = *(const ulonglong2*)(wr + 48);
#pragma unroll
                for (int qq = 0; qq < 2; qq++) {
                    o2[qq][0] = fma2(m2[qq][fi], wa.x, o2[qq][0]);
                    o2[qq][1] = fma2(m2[qq][fi], wa.y, o2[qq][1]);
                    o2[qq][2] = fma2(m2[qq][fi], wb.x, o2[qq][2]);
                    o2[qq][3] = fma2(m2[qq][fi], wb.y, o2[qq][3]);
                    o2[qq][4] = fma2(m2[qq][fi], wc.x, o2[qq][4]);
                    o2[qq][5] = fma2(m2[qq][fi], wc.y, o2[qq][5]);
                    o2[qq][6] = fma2(m2[qq][fi], wd.x, o2[qq][6]);
                    o2[qq][7] = fma2(m2[qq][fi], wd.y, o2[qq][7]);
                }
            }
            // split + store T hi/lo
#pragma unroll
            for (int qq = 0; qq < 2; qq++) {
                const int ca = c0 + (2 * qq) * 4;
                const int cb2 = c0 + (2 * qq + 1) * 4;
#pragma unroll
                for (int f = 0; f < 8; f++) {
                    float x0, x1;
                    upk2(o2[qq][f], x0, x1);
                    __nv_bfloat16 h0 = __float2bfloat16(x0);
                    __nv_bfloat16 l0 = __float2bfloat16(x0 - __bfloat162float(h0));
                    uint32_t oA = SW128((uint32_t)((ca * 8 + f) * 128 + nn * 2));
                    *(__nv_bfloat16*)(sm + OFF_THI + oA) = h0;
                    *(__nv_bfloat16*)(sm + OFF_TLO + oA) = l0;
                    __nv_bfloat16 h1 = __float2bfloat16(x1);
                    __nv_bfloat16 l1 = __float2bfloat16(x1 - __bfloat162float(h1));
                    uint32_t oB = SW128((uint32_t)((cb2 * 8 + f) * 128 + nn * 2));
                    *(__nv_bfloat16*)(sm + OFF_THI + oB) = h1;
                    *(__nv_bfloat16*)(sm + OFF_TLO + oB) = l1;
                }
            }
        }
        __syncthreads();

        // app2: R = T @ adj^T ; X += R in place
        warp_app<true>(smb, sm, Uf, OFF_THI, OFF_TLO, wid, lane);
        __syncwarp();
    }
    __syncthreads();

    // ---- tail: t[m][c] = sum_f X[(c,f)][m]*tw[f]; out = leaky(adj @ t) ----
    for (int i = tid; i < 4096; i += 256) {
        int l = i >> 6, m = i & 63;
        Uf[m * 68 + l] = adj[i];  // clobbers T (consumed)
    }
    float* tS = Uf + 64 * 68;  // [64 m][17]
    __syncthreads();
#pragma unroll
    for (int p = 0; p < 4; p++) {
        int idx = tid + p * 256;
        int m = idx & 63, c = idx >> 6;
        float s = 0.f;
#pragma unroll
        for (int f = 0; f < 8; f++) {
            uint32_t off = SW128((uint32_t)((c * 8 + f) * 128 + m * 2));
            float xv = __bfloat162float(*(__nv_bfloat16*)(sm + OFF_XHI + off))
                     + __bfloat162float(*(__nv_bfloat16*)(sm + OFF_XLO + off));
            s = fmaf(xv, WB[8 + f], s);
        }
        tS[m * 17 + c] = s;
    }
    __syncthreads();
    {
        const int l0 = wid * 8 + (lane >> 4) * 4;
        const int c = lane & 15;
        float g4[4] = {0.f, 0.f, 0.f, 0.f};
#pragma unroll 8
        for (int m = 0; m < 64; m++) {
            float fv = tS[m * 17 + c];
            float4 a = *(const float4*)(Uf + m * 68 + l0);
            g4[0] = fmaf(a.x, fv, g4[0]); g4[1] = fmaf(a.y, fv, g4[1]);
            g4[2] = fmaf(a.z, fv, g4[2]); g4[3] = fmaf(a.w, fv, g4[3]);
        }
#pragma unroll
        for (int i = 0; i < 4; i++) gout[(l0 + i) * 64 + c] = leaky(g4[i]);
    }
}

// ============================================================================
// Kernel 3: gather + fuse 1x1 conv + bias + residual (FFMA2 GEMM loop)
// ============================================================================
__global__ __launch_bounds__(256) void k_fuse(
    const float* __restrict__ x, const float* __restrict__ fuse_w,
    const float* __restrict__ fuse_b, float* __restrict__ out)
{
    extern __shared__ float sm_fuse[];
    float* as = sm_fuse;
    float* ws = sm_fuse + 128 * 68;
    const int tid = threadIdx.x;
    const int b = blockIdx.x >> 6, h = blockIdx.x & 63;

    const float* gh = g_gout[0] + (size_t)blockIdx.x * 4096;
    for (int i = tid; i < 4096; i += 256) {
        int w = i >> 6, c = i & 63;
        as[c * 68 + w] = gh[i];
    }
    const float* gvbase = g_gout[1] + (size_t)b * 64 * 4096 + h * 64;
    for (int i = tid; i < 4096; i += 256) {
        int w = i >> 6, c = i & 63;
        as[(64 + c) * 68 + w] = gvbase[(size_t)w * 4096 + c];
    }
    for (int i = tid; i < 128 * 128; i += 256) {
        int oc = i >> 7, c = i & 127;
        ws[c * 132 + oc] = fuse_w[i];
    }
    __syncthreads();

    const int oc0 = (tid >> 4) * 8;
    const int w0 = (tid & 15) * 4;
    uint64_t acc2[16];
#pragma unroll
    for (int i = 0; i < 16; i++) acc2[i] = 0ull;
#pragma unroll 4
    for (int c = 0; c < 128; c++) {
        float4 a0 = *(const float4*)(ws + c * 132 + oc0);
        float4 a1 = *(const float4*)(ws + c * 132 + oc0 + 4);
        ulonglong2 bv = *(const ulonglong2*)(as + c * 68 + w0);
        uint64_t d;
        d = pk2(a0.x, a0.x); acc2[0]  = fma2(d, bv.x, acc2[0]);  acc2[1]  = fma2(d, bv.y, acc2[1]);
        d = pk2(a0.y, a0.y); acc2[2]  = fma2(d, bv.x, acc2[2]);  acc2[3]  = fma2(d, bv.y, acc2[3]);
        d = pk2(a0.z, a0.z); acc2[4]  = fma2(d, bv.x, acc2[4]);  acc2[5]  = fma2(d, bv.y, acc2[5]);
        d = pk2(a0.w, a0.w); acc2[6]  = fma2(d, bv.x, acc2[6]);  acc2[7]  = fma2(d, bv.y, acc2[7]);
        d = pk2(a1.x, a1.x); acc2[8]  = fma2(d, bv.x, acc2[8]);  acc2[9]  = fma2(d, bv.y, acc2[9]);
        d = pk2(a1.y, a1.y); acc2[10] = fma2(d, bv.x, acc2[10]); acc2[11] = fma2(d, bv.y, acc2[11]);
        d = pk2(a1.z, a1.z); acc2[12] = fma2(d, bv.x, acc2[12]); acc2[13] = fma2(d, bv.y, acc2[13]);
        d = pk2(a1.w, a1.w); acc2[14] = fma2(d, bv.x, acc2[14]); acc2[15] = fma2(d, bv.y, acc2[15]);
    }
    const float* xblk = x + (size_t)b * 128 * 4096 + h * 64;
    float* oblk = out + (size_t)b * 128 * 4096 + h * 64;
#pragma unroll
    for (int i = 0; i < 8; i++) {
        int oc = oc0 + i;
        float bia = fuse_b[oc];
        float v0, v1, v2, v3;
        upk2(acc2[2 * i], v0, v1);
        upk2(acc2[2 * i + 1], v2, v3);
        float4 xv = *(const float4*)(xblk + (size_t)oc * 4096 + w0);
        *(float4*)(oblk + (size_t)oc * 4096 + w0) =
            make_float4(v0 + bia + xv.x, v1 + bia + xv.y,
                        v2 + bia + xv.z, v3 + bia + xv.w);
    }
}

extern "C" void kernel_launch(void* const* d_in, const int* in_sizes, int n_in,
                              void* d_out, int out_size)
{
    const float* x      = (const float*)d_in[0];
    const float* adj_h  = (const float*)d_in[1];
    const float* adj_v  = (const float*)d_in[2];
    const float* norm_w = (const float*)d_in[3];
    const float* norm_b = (const float*)d_in[4];
    const float* conv_w = (const float*)d_in[5];
    const float* conv_b = (const float*)d_in[6];
    const float* fuse_w = (const float*)d_in[7];
    const float* fuse_b = (const float*)d_in[8];
    const float* head_h = (const float*)d_in[9];
    const float* tail_h = (const float*)d_in[10];
    const float* w1_h   = (const float*)d_in[11];
    const float* w2_h   = (const float*)d_in[12];
    const float* head_v = (const float*)d_in[13];
    const float* tail_v = (const float*)d_in[14];
    const float* w1_v   = (const float*)d_in[15];
    const float* w2_v   = (const float*)d_in[16];
    float* out = (float*)d_out;

    const size_t s_pre  = (size_t)(128 * 64 + 128 * 132 + 128) * sizeof(float);
    const size_t s_fuse = (size_t)(128 * 68 + 128 * 132) * sizeof(float);
    cudaFuncSetAttribute(k_pre, cudaFuncAttributeMaxDynamicSharedMemorySize, (int)s_pre);
    cudaFuncSetAttribute(k_gcm, cudaFuncAttributeMaxDynamicSharedMemorySize, (int)GCM_SMEM);
    cudaFuncSetAttribute(k_fuse, cudaFuncAttributeMaxDynamicSharedMemorySize, (int)s_fuse);

    k_pre<<<256, 256, s_pre>>>(x, norm_w, norm_b, conv_w, conv_b);
    k_gcm<<<dim3(256, 4, 2), 256, GCM_SMEM>>>(adj_h, adj_v, head_h, tail_h, w1_h, w2_h,
                                              head_v, tail_v, w1_v, w2_v);
    k_fuse<<<256, 256, s_fuse>>>(x, fuse_w, fuse_b, out);
}

// round 10
// speedup vs baseline: 1.7550x; 1.1156x over previous
#include <cuda_runtime.h>
#include <cuda_bf16.h>
#include <cstdint>

#define LRELU_SLOPE 0.2f

// Scratch: [dir][graph(256)][node(64)][ch(64)]
__device__ float g_feat[2][256 * 64 * 64];
__device__ float g_gout[2][256 * 64 * 64];

__device__ __forceinline__ float leaky(float v) { return v >= 0.f ? v : LRELU_SLOPE * v; }

__device__ __forceinline__ void f4fma(float a, const float4& b, float4& c) {
    c.x = fmaf(a, b.x, c.x); c.y = fmaf(a, b.y, c.y);
    c.z = fmaf(a, b.z, c.z); c.w = fmaf(a, b.w, c.w);
}

// ---- packed f32x2 helpers ----
__device__ __forceinline__ uint64_t pk2(float x, float y) {
    uint64_t r; asm("mov.b64 %0, {%1, %2};" : "=l"(r) : "f"(x), "f"(y)); return r;
}
__device__ __forceinline__ void upk2(uint64_t v, float& x, float& y) {
    asm("mov.b64 {%0, %1}, %2;" : "=f"(x), "=f"(y) : "l"(v));
}
__device__ __forceinline__ uint64_t fma2(uint64_t a, uint64_t b, uint64_t c) {
    uint64_t d; asm("fma.rn.f32x2 %0, %1, %2, %3;" : "=l"(d) : "l"(a), "l"(b), "l"(c)); return d;
}

__device__ __forceinline__ uint32_t smem_u32(const void* p) {
    uint32_t a;
    asm("{ .reg .u64 t; cvta.to.shared.u64 t, %1; cvt.u32.u64 %0, t; }" : "=r"(a) : "l"(p));
    return a;
}
#define SW128(o) ((o) ^ (((o) >> 3) & 0x70))

__device__ __forceinline__ void ldsm4(uint32_t r[4], uint32_t addr) {
    asm volatile("ldmatrix.sync.aligned.m8n8.x4.shared.b16 {%0,%1,%2,%3}, [%4];"
                 : "=r"(r[0]), "=r"(r[1]), "=r"(r[2]), "=r"(r[3]) : "r"(addr));
}
__device__ __forceinline__ void mma16816(float c[4], const uint32_t a[4], uint32_t b0, uint32_t b1) {
    asm volatile(
        "mma.sync.aligned.m16n8k16.row.col.f32.bf16.bf16.f32 "
        "{%0,%1,%2,%3}, {%4,%5,%6,%7}, {%8,%9}, {%0,%1,%2,%3};"
        : "+f"(c[0]), "+f"(c[1]), "+f"(c[2]), "+f"(c[3])
        : "r"(a[0]), "r"(a[1]), "r"(a[2]), "r"(a[3]), "r"(b0), "r"(b1));
}

// ============================================================================
// Kernel 1: LayerNorm + 1x1 conv + leaky + strip split
// ============================================================================
__global__ __launch_bounds__(256) void k_pre(
    const float* __restrict__ x, const float* __restrict__ norm_w,
    const float* __restrict__ norm_b, const float* __restrict__ conv_w,
    const float* __restrict__ conv_b)
{
    extern __shared__ float sm_pre[];
    float* xs = sm_pre;
    float* ws = sm_pre + 128 * 64;
    float* mu = ws + 128 * 132;
    float* rs = mu + 64;
    const int tid = threadIdx.x;
    const int b = blockIdx.x >> 6, h = blockIdx.x & 63;
    const float* xblk = x + (size_t)b * 128 * 4096 + h * 64;

    for (int i = tid; i < 128 * 64; i += 256) {
        int c = i >> 6, w = i & 63;
        xs[i] = xblk[c * 4096 + w];
    }
    for (int i = tid; i < 128 * 128; i += 256) {
        int oc = i >> 7, c = i & 127;
        ws[c * 132 + oc] = conv_w[i];
    }
    __syncthreads();
    if (tid < 64) {
        float s = 0.f, s2 = 0.f;
#pragma unroll 8
        for (int c = 0; c < 128; c++) { float v = xs[c * 64 + tid]; s += v; s2 += v * v; }
        float m = s * 0.0078125f;
        float var = s2 * 0.0078125f - m * m;
        mu[tid] = m; rs[tid] = rsqrtf(var + 1e-5f);
    }
    __syncthreads();
    for (int i = tid; i < 128 * 64; i += 256) {
        int c = i >> 6, w = i & 63;
        xs[i] = (xs[i] - mu[w]) * rs[w] * norm_w[c] + norm_b[c];
    }
    __syncthreads();

    const int oc0 = (tid >> 4) * 8;
    const int w0 = (tid & 15) * 4;
    uint64_t acc2[16];
#pragma unroll
    for (int i = 0; i < 16; i++) acc2[i] = 0ull;
#pragma unroll 4
    for (int c = 0; c < 128; c++) {
        float4 a0 = *(const float4*)(ws + c * 132 + oc0);
        float4 a1 = *(const float4*)(ws + c * 132 + oc0 + 4);
        ulonglong2 bv = *(const ulonglong2*)(xs + c * 64 + w0);
        uint64_t d;
        d = pk2(a0.x, a0.x); acc2[0]  = fma2(d, bv.x, acc2[0]);  acc2[1]  = fma2(d, bv.y, acc2[1]);
        d = pk2(a0.y, a0.y); acc2[2]  = fma2(d, bv.x, acc2[2]);  acc2[3]  = fma2(d, bv.y, acc2[3]);
        d = pk2(a0.z, a0.z); acc2[4]  = fma2(d, bv.x, acc2[4]);  acc2[5]  = fma2(d, bv.y, acc2[5]);
        d = pk2(a0.w, a0.w); acc2[6]  = fma2(d, bv.x, acc2[6]);  acc2[7]  = fma2(d, bv.y, acc2[7]);
        d = pk2(a1.x, a1.x); acc2[8]  = fma2(d, bv.x, acc2[8]);  acc2[9]  = fma2(d, bv.y, acc2[9]);
        d = pk2(a1.y, a1.y); acc2[10] = fma2(d, bv.x, acc2[10]); acc2[11] = fma2(d, bv.y, acc2[11]);
        d = pk2(a1.z, a1.z); acc2[12] = fma2(d, bv.x, acc2[12]); acc2[13] = fma2(d, bv.y, acc2[13]);
        d = pk2(a1.w, a1.w); acc2[14] = fma2(d, bv.x, acc2[14]); acc2[15] = fma2(d, bv.y, acc2[15]);
    }
    float av[8][4];
#pragma unroll
    for (int i = 0; i < 8; i++) {
        upk2(acc2[2 * i], av[i][0], av[i][1]);
        upk2(acc2[2 * i + 1], av[i][2], av[i][3]);
        float bia = conv_b[oc0 + i];
#pragma unroll
        for (int j = 0; j < 4; j++) av[i][j] = leaky(av[i][j] + bia);
    }
    if (oc0 < 64) {
#pragma unroll
        for (int j = 0; j < 4; j++) {
            int w = w0 + j;
            float* dst = g_feat[0] + ((size_t)blockIdx.x * 64 + w) * 64 + oc0;
            *(float4*)dst = make_float4(av[0][j], av[1][j], av[2][j], av[3][j]);
            *(float4*)(dst + 4) = make_float4(av[4][j], av[5][j], av[6][j], av[7][j]);
        }
    } else {
#pragma unroll
        for (int j = 0; j < 4; j++) {
            int w = w0 + j;
            float* dst = g_feat[1] + ((size_t)(b * 64 + w) * 64 + h) * 64 + (oc0 - 64);
            *(float4*)dst = make_float4(av[0][j], av[1][j], av[2][j], av[3][j]);
            *(float4*)(dst + 4) = make_float4(av[4][j], av[5][j], av[6][j], av[7][j]);
        }
    }
}

// ============================================================================
// GCM via warp-level mma.sync bf16 3-term split. CH-TILE = 16, 2 CTAs/SM.
// Head and tail adj-GEMMs also on MMA (B = 16-row operand in T region).
// ============================================================================
#define OFF_AHI 0u
#define OFF_ALO 8192u
#define OFF_XHI 16384u
#define OFF_XLO 32768u
#define OFF_THI 49152u
#define OFF_TLO 65536u
#define OFF_U   49152u
#define OFF_FBH 49152u            // 16-row B operand hi (head: feat^T, tail: t^T)
#define OFF_FBL 51200u            // 16-row B operand lo
#define OFF_GS  57344u            // gS fp32 [64][18] (head output)
#define OFF_WB  83968u
#define OFF_W2B 86080u
#define GCM_SMEM 90176u

template <bool RESID>
__device__ __forceinline__ void warp_app(uint32_t smb, char* smc, float* __restrict__ Uf,
                                         uint32_t aHiOff, uint32_t aLoOff,
                                         int wid, int lane)
{
    float c[8][4];
#pragma unroll
    for (int nt = 0; nt < 8; nt++)
#pragma unroll
        for (int j = 0; j < 4; j++) c[nt][j] = 0.f;

    const int warpM = wid * 16;
    const uint32_t aRow = warpM + (lane & 15);
    const uint32_t aK8 = (lane >> 4) * 8;
    const int q = lane >> 3;
    const uint32_t bRow = (lane & 7) + ((q >> 1) * 8);
    const uint32_t bK8 = (q & 1) * 8;

#pragma unroll
    for (int ks = 0; ks < 4; ks++) {
        const uint32_t ao = SW128(aRow * 128 + (ks * 16 + aK8) * 2);
        uint32_t aH[4], aL[4];
        ldsm4(aH, smb + aHiOff + ao);
        ldsm4(aL, smb + aLoOff + ao);
#pragma unroll
        for (int nt2 = 0; nt2 < 4; nt2++) {
            const uint32_t bo = SW128((nt2 * 16 + bRow) * 128 + (ks * 16 + bK8) * 2);
            uint32_t bH[4], bL[4];
            ldsm4(bH, smb + OFF_AHI + bo);
            ldsm4(bL, smb + OFF_ALO + bo);
            mma16816(c[nt2 * 2 + 0], aH, bH[0], bH[1]);
            mma16816(c[nt2 * 2 + 1], aH, bH[2], bH[3]);
            mma16816(c[nt2 * 2 + 0], aH, bL[0], bL[1]);
            mma16816(c[nt2 * 2 + 1], aH, bL[2], bL[3]);
            mma16816(c[nt2 * 2 + 0], aL, bH[0], bH[1]);
            mma16816(c[nt2 * 2 + 1], aL, bH[2], bH[3]);
        }
    }

    const int rg = lane >> 2, cg = (lane & 3) * 2;
    if (!RESID) {
#pragma unroll
        for (int nt = 0; nt < 8; nt++) {
            const int col = nt * 8 + cg;
            const int row0 = warpM + rg;
            *(float2*)&Uf[row0 * 68 + col] = make_float2(c[nt][0], c[nt][1]);
            *(float2*)&Uf[(row0 + 8) * 68 + col] = make_float2(c[nt][2], c[nt][3]);
        }
    } else {
#pragma unroll
        for (int nt = 0; nt < 8; nt++) {
            const int col = nt * 8 + cg;
#pragma unroll
            for (int hh = 0; hh < 2; hh++) {
                const int row = warpM + rg + hh * 8;
                const uint32_t off = SW128((uint32_t)(row * 128 + col * 2));
                __nv_bfloat162 h2 = *(__nv_bfloat162*)(smc + OFF_XHI + off);
                __nv_bfloat162 l2 = *(__nv_bfloat162*)(smc + OFF_XLO + off);
                float x0 = __bfloat162float(h2.x) + __bfloat162float(l2.x) + c[nt][hh * 2];
                float x1 = __bfloat162float(h2.y) + __bfloat162float(l2.y) + c[nt][hh * 2 + 1];
                __nv_bfloat16 nh0 = __float2bfloat16(x0);
                __nv_bfloat16 nl0 = __float2bfloat16(x0 - __bfloat162float(nh0));
                __nv_bfloat16 nh1 = __float2bfloat16(x1);
                __nv_bfloat16 nl1 = __float2bfloat16(x1 - __bfloat162float(nh1));
                __nv_bfloat162 oh; oh.x = nh0; oh.y = nh1;
                __nv_bfloat162 ol; ol.x = nl0; ol.y = nl1;
                *(__nv_bfloat162*)(smc + OFF_XHI + off) = oh;
                *(__nv_bfloat162*)(smc + OFF_XLO + off) = ol;
            }
        }
    }
}

// Small MMA: D[64 l][16 c] = adj @ B16, 3-term split. Warp w: m-tile (w&3), n-tile (w>>2).
__device__ __forceinline__ void small_mma(uint32_t smb, int wid, int lane, float ch[4])
{
    const int hwM = (wid & 3) * 16;
    const int hnt = wid >> 2;
    const uint32_t aRow = hwM + (lane & 15);
    const uint32_t aK8 = (lane >> 4) * 8;
    const int q = lane >> 3;
    const uint32_t bRow = (lane & 7) + ((q >> 1) * 8);
    const uint32_t bK8 = (q & 1) * 8;
    ch[0] = ch[1] = ch[2] = ch[3] = 0.f;
#pragma unroll
    for (int ks = 0; ks < 4; ks++) {
        uint32_t ao = SW128(aRow * 128 + (ks * 16 + aK8) * 2);
        uint32_t aH[4], aL[4];
        ldsm4(aH, smb + OFF_AHI + ao);
        ldsm4(aL, smb + OFF_ALO + ao);
        uint32_t bo = SW128(bRow * 128 + (ks * 16 + bK8) * 2);
        uint32_t bH[4], bL[4];
        ldsm4(bH, smb + OFF_FBH + bo);
        ldsm4(bL, smb + OFF_FBL + bo);
        uint32_t b0H = hnt ? bH[2] : bH[0], b1H = hnt ? bH[3] : bH[1];
        uint32_t b0L = hnt ? bL[2] : bL[0], b1L = hnt ? bL[3] : bL[1];
        mma16816(ch, aH, b0H, b1H);
        mma16816(ch, aH, b0L, b1L);
        mma16816(ch, aL, b0H, b1H);
    }
}

__device__ __forceinline__ void store_row_split32(char* smc, uint32_t hiOff, uint32_t loOff,
                                                  int r, int cb, const float* v) {
    const uint32_t rowb = (uint32_t)r * 128;
#pragma unroll
    for (int j = 0; j < 32; j += 8) {
        ushort hi[8], lo[8];
#pragma unroll
        for (int qq = 0; qq < 8; qq++) {
            float x = v[j + qq];
            __nv_bfloat16 h = __float2bfloat16(x);
            __nv_bfloat16 l = __float2bfloat16(x - __bfloat162float(h));
            hi[qq] = *(ushort*)&h; lo[qq] = *(ushort*)&l;
        }
        uint32_t o = SW128(rowb + (cb + j) * 2);
        *(uint4*)(smc + hiOff + o) = *(uint4*)hi;
        *(uint4*)(smc + loOff + o) = *(uint4*)lo;
    }
}

__global__ __launch_bounds__(256, 2) void k_gcm(
    const float* __restrict__ adj_h, const float* __restrict__ adj_v,
    const float* __restrict__ head_h, const float* __restrict__ tail_h,
    const float* __restrict__ w1_h, const float* __restrict__ w2_h,
    const float* __restrict__ head_v, const float* __restrict__ tail_v,
    const float* __restrict__ w1_v, const float* __restrict__ w2_v)
{
    extern __shared__ __align__(1024) char sm[];
    const uint32_t smb = smem_u32(sm);
    float* Uf = (float*)(sm + OFF_U);     // [128][68] fp32 (aliases THI/TLO)
    float* WB = (float*)(sm + OFF_WB);
    float* gS = (float*)(sm + OFF_GS);    // [64][18]
    const int tid = threadIdx.x;
    const int wid = tid >> 5, lane = tid & 31;
    const int graph = blockIdx.x, ct = blockIdx.y, dir = blockIdx.z;
    const float* adj = dir ? adj_v : adj_h;
    const float* hw = dir ? head_v : head_h;
    const float* tw = dir ? tail_v : tail_h;
    const float* w1 = dir ? w1_v : w1_h;
    const float* w2 = dir ? w2_v : w2_h;
    const float* feat = g_feat[dir] + (size_t)graph * 4096 + ct * 16;
    float* gout = g_gout[dir] + (size_t)graph * 4096 + ct * 16;

    // ---- stage adj bf16 hi/lo + feat^T operand + weights ----
    for (int i = tid; i < 4096; i += 256) {
        int l = i >> 6, m = i & 63;
        float v = adj[i];
        __nv_bfloat16 h = __float2bfloat16(v);
        __nv_bfloat16 lo = __float2bfloat16(v - __bfloat162float(h));
        uint32_t o = SW128((uint32_t)(l * 128 + m * 2));
        *(__nv_bfloat16*)(sm + OFF_AHI + o) = h;
        *(__nv_bfloat16*)(sm + OFF_ALO + o) = lo;
    }
    for (int i = tid; i < 1024; i += 256) {
        int m = i >> 4, c = i & 15;
        float v = feat[m * 64 + c];
        __nv_bfloat16 h = __float2bfloat16(v);
        __nv_bfloat16 lo = __float2bfloat16(v - __bfloat162float(h));
        uint32_t o = SW128((uint32_t)(c * 128 + m * 2));
        *(__nv_bfloat16*)(sm + OFF_FBH + o) = h;
        *(__nv_bfloat16*)(sm + OFF_FBL + o) = lo;
    }
    for (int i = tid; i < 528; i += 256) {
        float v;
        if (i < 8) v = hw[i];
        else if (i < 16) v = tw[i - 8];
        else if (i < 272) v = w1[i - 16];
        else v = w2[i - 272];
        WB[i] = v;
    }
    for (int i = tid; i < 512; i += 256) {
        int it = i >> 7, rest = i & 127;
        int s = rest >> 6, idx = rest & 63;
        float v = s ? w2[it * 64 + idx] : w1[it * 64 + idx];
        *(float2*)(sm + OFF_W2B + (size_t)i * 8) = make_float2(v, v);
    }
    __syncthreads();

    // ---- head: g = adj @ feat via small MMA ----
    {
        float ch[4];
        small_mma(smb, wid, lane, ch);
        const int rg = lane >> 2, cg = (lane & 3) * 2;
        const int col = (wid >> 2) * 8 + cg;
        const int row = (wid & 3) * 16 + rg;
        *(float2*)&gS[row * 18 + col] = make_float2(ch[0], ch[1]);
        *(float2*)&gS[(row + 8) * 18 + col] = make_float2(ch[2], ch[3]);
    }
    __syncthreads();

    // X[r][l] = g[l][c] * hw[f]  -> XHI/XLO
    {
        const int r = tid >> 1, half = tid & 1;
        const int c = r >> 3, f = r & 7;
        const float hf = WB[f];
        const int cb = half * 32;
        float v[32];
#pragma unroll
        for (int l = 0; l < 32; l++) v[l] = gS[(cb + l) * 18 + c] * hf;
        store_row_split32(sm, OFF_XHI, OFF_XLO, r, cb, v);
    }
    __syncthreads();

    const int nn = tid & 63;
    const int c0 = tid >> 6;  // cc[p] = c0 + p*4

    // ---- ResGCN body ----
    for (int it = 0; it < 4; it++) {
        // app1: U = X @ adj^T -> Uf
        warp_app<false>(smb, sm, Uf, OFF_XHI, OFF_XLO, wid, lane);
        __syncthreads();

        // fmix: T = leaky(U W1) W2 -> THI/TLO (packed f32x2)
        {
            float vi[4][8];
#pragma unroll
            for (int p = 0; p < 4; p++) {
                int cc = c0 + p * 4;
#pragma unroll
                for (int f = 0; f < 8; f++) vi[p][f] = Uf[(cc * 8 + f) * 68 + nn];
            }
            __syncthreads();  // Uf reads done before T writes (alias)

            uint64_t V[2][8];
#pragma unroll
            for (int qq = 0; qq < 2; qq++)
#pragma unroll
                for (int f = 0; f < 8; f++) V[qq][f] = pk2(vi[2 * qq][f], vi[2 * qq + 1][f]);

            const char* wbase = sm + OFF_W2B + it * 1024;
            uint64_t m2[2][8];
#pragma unroll
            for (int qq = 0; qq < 2; qq++)
#pragma unroll
                for (int f = 0; f < 8; f++) m2[qq][f] = 0ull;
#pragma unroll
            for (int fi = 0; fi < 8; fi++) {
                const char* wr = wbase + fi * 64;
                ulonglong2 wa = *(const ulonglong2*)(wr);
                ulonglong2 wb = *(const ulonglong2*)(wr + 16);
                ulonglong2 wc = *(const ulonglong2*)(wr + 32);
                ulonglong2 wd = *(const ulonglong2*)(wr + 48);
#pragma unroll
                for (int qq = 0; qq < 2; qq++) {
                    m2[qq][0] = fma2(V[qq][fi], wa.x, m2[qq][0]);
                    m2[qq][1] = fma2(V[qq][fi], wa.y, m2[qq][1]);
                    m2[qq][2] = fma2(V[qq][fi], wb.x, m2[qq][2]);
                    m2[qq][3] = fma2(V[qq][fi], wb.y, m2[qq][3]);
                    m2[qq][4] = fma2(V[qq][fi], wc.x, m2[qq][4]);
                    m2[qq][5] = fma2(V[qq][fi], wc.y, m2[qq][5]);
                    m2[qq][6] = fma2(V[qq][fi], wd.x, m2[qq][6]);
                    m2[qq][7] = fma2(V[qq][fi], wd.y, m2[qq][7]);
                }
            }
#pragma unroll
            for (int qq = 0; qq < 2; qq++)
#pragma unroll
                for (int f = 0; f < 8; f++) {
                    float a, b2;
                    upk2(m2[qq][f], a, b2);
                    m2[qq][f] = pk2(leaky(a), leaky(b2));
                }
            const char* wbase2 = wbase + 512;
            uint64_t o2[2][8];
#pragma unroll
            for (int qq = 0; qq < 2; qq++)
#pragma unroll
                for (int f = 0; f < 8; f++) o2[qq][f] = 0ull;
#pragma unroll
            for (int fi = 0; fi < 8; fi++) {
                const char* wr = wbase2 + fi * 64;
                ulonglong2 wa = *(const ulonglong2*)(wr);
                ulonglong2 wb = *(const ulonglong2*)(wr + 16);
                ulonglong2 wc = *(const ulonglong2*)(wr + 32);
                ulonglong2 wd = *(const ulonglong2*)(wr + 48);
#pragma unroll
                for (int qq = 0; qq < 2; qq++) {
                    o2[qq][0] = fma2(m2[qq][fi], wa.x, o2[qq][0]);
                    o2[qq][1] = fma2(m2[qq][fi], wa.y, o2[qq][1]);
                    o2[qq][2] = fma2(m2[qq][fi], wb.x, o2[qq][2]);
                    o2[qq][3] = fma2(m2[qq][fi], wb.y, o2[qq][3]);
                    o2[qq][4] = fma2(m2[qq][fi], wc.x, o2[qq][4]);
                    o2[qq][5] = fma2(m2[qq][fi], wc.y, o2[qq][5]);
                    o2[qq][6] = fma2(m2[qq][fi], wd.x, o2[qq][6]);
                    o2[qq][7] = fma2(m2[qq][fi], wd.y, o2[qq][7]);
                }
            }
#pragma unroll
            for (int qq = 0; qq < 2; qq++) {
                const int ca = c0 + (2 * qq) * 4;
                const int cb2 = c0 + (2 * qq + 1) * 4;
#pragma unroll
                for (int f = 0; f < 8; f++) {
                    float x0, x1;
                    upk2(o2[qq][f], x0, x1);
                    __nv_bfloat16 h0 = __float2bfloat16(x0);
                    __nv_bfloat16 l0 = __float2bfloat16(x0 - __bfloat162float(h0));
                    uint32_t oA = SW128((uint32_t)((ca * 8 + f) * 128 + nn * 2));
                    *(__nv_bfloat16*)(sm + OFF_THI + oA) = h0;
                    *(__nv_bfloat16*)(sm + OFF_TLO + oA) = l0;
                    __nv_bfloat16 h1 = __float2bfloat16(x1);
                    __nv_bfloat16 l1 = __float2bfloat16(x1 - __bfloat162float(h1));
                    uint32_t oB = SW128((uint32_t)((cb2 * 8 + f) * 128 + nn * 2));
                    *(__nv_bfloat16*)(sm + OFF_THI + oB) = h1;
                    *(__nv_bfloat16*)(sm + OFF_TLO + oB) = l1;
                }
            }
        }
        __syncthreads();

        // app2: R = T @ adj^T ; X += R in place
        warp_app<true>(smb, sm, Uf, OFF_THI, OFF_TLO, wid, lane);
        __syncwarp();
        __syncthreads();
    }

    // ---- tail: t[m][c] = sum_f X[(c,f)][m]*tw[f] -> bf16 split B operand ----
#pragma unroll
    for (int p = 0; p < 4; p++) {
        int idx = tid + p * 256;
        int m = idx & 63, c = idx >> 6;
        float s = 0.f;
#pragma unroll
        for (int f = 0; f < 8; f++) {
            uint32_t off = SW128((uint32_t)((c * 8 + f) * 128 + m * 2));
            float xv = __bfloat162float(*(__nv_bfloat16*)(sm + OFF_XHI + off))
                     + __bfloat162float(*(__nv_bfloat16*)(sm + OFF_XLO + off));
            s = fmaf(xv, WB[8 + f], s);
        }
        __nv_bfloat16 h = __float2bfloat16(s);
        __nv_bfloat16 l = __float2bfloat16(s - __bfloat162float(h));
        uint32_t o = SW128((uint32_t)(c * 128 + m * 2));
        *(__nv_bfloat16*)(sm + OFF_FBH + o) = h;
        *(__nv_bfloat16*)(sm + OFF_FBL + o) = l;
    }
    __syncthreads();

    // out = leaky(adj @ t) via small MMA, straight to gout
    {
        float ch[4];
        small_mma(smb, wid, lane, ch);
        const int rg = lane >> 2, cg = (lane & 3) * 2;
        const int col = (wid >> 2) * 8 + cg;
        const int row = (wid & 3) * 16 + rg;
        *(float2*)&gout[row * 64 + col] = make_float2(leaky(ch[0]), leaky(ch[1]));
        *(float2*)&gout[(row + 8) * 64 + col] = make_float2(leaky(ch[2]), leaky(ch[3]));
    }
}

// ============================================================================
// Kernel 3: gather + fuse 1x1 conv + bias + residual
// ============================================================================
__global__ __launch_bounds__(256) void k_fuse(
    const float* __restrict__ x, const float* __restrict__ fuse_w,
    const float* __restrict__ fuse_b, float* __restrict__ out)
{
    extern __shared__ float sm_fuse[];
    float* as = sm_fuse;
    float* ws = sm_fuse + 128 * 68;
    const int tid = threadIdx.x;
    const int b = blockIdx.x >> 6, h = blockIdx.x & 63;

    const float* gh = g_gout[0] + (size_t)blockIdx.x * 4096;
    for (int i = tid; i < 4096; i += 256) {
        int w = i >> 6, c = i & 63;
        as[c * 68 + w] = gh[i];
    }
    const float* gvbase = g_gout[1] + (size_t)b * 64 * 4096 + h * 64;
    for (int i = tid; i < 4096; i += 256) {
        int w = i >> 6, c = i & 63;
        as[(64 + c) * 68 + w] = gvbase[(size_t)w * 4096 + c];
    }
    for (int i = tid; i < 128 * 128; i += 256) {
        int oc = i >> 7, c = i & 127;
        ws[c * 132 + oc] = fuse_w[i];
    }
    __syncthreads();

    const int oc0 = (tid >> 4) * 8;
    const int w0 = (tid & 15) * 4;
    uint64_t acc2[16];
#pragma unroll
    for (int i = 0; i < 16; i++) acc2[i] = 0ull;
#pragma unroll 4
    for (int c = 0; c < 128; c++) {
        float4 a0 = *(const float4*)(ws + c * 132 + oc0);
        float4 a1 = *(const float4*)(ws + c * 132 + oc0 + 4);
        ulonglong2 bv = *(const ulonglong2*)(as + c * 68 + w0);
        uint64_t d;
        d = pk2(a0.x, a0.x); acc2[0]  = fma2(d, bv.x, acc2[0]);  acc2[1]  = fma2(d, bv.y, acc2[1]);
        d = pk2(a0.y, a0.y); acc2[2]  = fma2(d, bv.x, acc2[2]);  acc2[3]  = fma2(d, bv.y, acc2[3]);
        d = pk2(a0.z, a0.z); acc2[4]  = fma2(d, bv.x, acc2[4]);  acc2[5]  = fma2(d, bv.y, acc2[5]);
        d = pk2(a0.w, a0.w); acc2[6]  = fma2(d, bv.x, acc2[6]);  acc2[7]  = fma2(d, bv.y, acc2[7]);
        d = pk2(a1.x, a1.x); acc2[8]  = fma2(d, bv.x, acc2[8]);  acc2[9]  = fma2(d, bv.y, acc2[9]);
        d = pk2(a1.y, a1.y); acc2[10] = fma2(d, bv.x, acc2[10]); acc2[11] = fma2(d, bv.y, acc2[11]);
        d = pk2(a1.z, a1.z); acc2[12] = fma2(d, bv.x, acc2[12]); acc2[13] = fma2(d, bv.y, acc2[13]);
        d = pk2(a1.w, a1.w); acc2[14] = fma2(d, bv.x, acc2[14]); acc2[15] = fma2(d, bv.y, acc2[15]);
    }
    const float* xblk = x + (size_t)b * 128 * 4096 + h * 64;
    float* oblk = out + (size_t)b * 128 * 4096 + h * 64;
#pragma unroll
    for (int i = 0; i < 8; i++) {
        int oc = oc0 + i;
        float bia = fuse_b[oc];
        float v0, v1, v2, v3;
        upk2(acc2[2 * i], v0, v1);
        upk2(acc2[2 * i + 1], v2, v3);
        float4 xv = *(const float4*)(xblk + (size_t)oc * 4096 + w0);
        *(float4*)(oblk + (size_t)oc * 4096 + w0) =
            make_float4(v0 + bia + xv.x, v1 + bia + xv.y,
                        v2 + bia + xv.z, v3 + bia + xv.w);
    }
}

extern "C" void kernel_launch(void* const* d_in, const int* in_sizes, int n_in,
                              void* d_out, int out_size)
{
    const float* x      = (const float*)d_in[0];
    const float* adj_h  = (const float*)d_in[1];
    const float* adj_v  = (const float*)d_in[2];
    const float* norm_w = (const float*)d_in[3];
    const float* norm_b = (const float*)d_in[4];
    const float* conv_w = (const float*)d_in[5];
    const float* conv_b = (const float*)d_in[6];
    const float* fuse_w = (const float*)d_in[7];
    const float* fuse_b = (const float*)d_in[8];
    const float* head_h = (const float*)d_in[9];
    const float* tail_h = (const float*)d_in[10];
    const float* w1_h   = (const float*)d_in[11];
    const float* w2_h   = (const float*)d_in[12];
    const float* head_v = (const float*)d_in[13];
    const float* tail_v = (const float*)d_in[14];
    const float* w1_v   = (const float*)d_in[15];
    const float* w2_v   = (const float*)d_in[16];
    float* out = (float*)d_out;

    const size_t s_pre  = (size_t)(128 * 64 + 128 * 132 + 128) * sizeof(float);
    const size_t s_fuse = (size_t)(128 * 68 + 128 * 132) * sizeof(float);
    cudaFuncSetAttribute(k_pre, cudaFuncAttributeMaxDynamicSharedMemorySize, (int)s_pre);
    cudaFuncSetAttribute(k_gcm, cudaFuncAttributeMaxDynamicSharedMemorySize, (int)GCM_SMEM);
    cudaFuncSetAttribute(k_fuse, cudaFuncAttributeMaxDynamicSharedMemorySize, (int)s_fuse);

    k_pre<<<256, 256, s_pre>>>(x, norm_w, norm_b, conv_w, conv_b);
    k_gcm<<<dim3(256, 4, 2), 256, GCM_SMEM>>>(adj_h, adj_v, head_h, tail_h, w1_h, w2_h,
                                              head_v, tail_v, w1_v, w2_v);
    k_fuse<<<256, 256, s_fuse>>>(x, fuse_w, fuse_b, out);
}